// round 13
// baseline (speedup 1.0000x reference)
#include <cuda_runtime.h>
#include <cuda_bf16.h>
#include <cuda_fp16.h>
#include <math.h>
#include <cstdint>

// ---------------------------------------------------------------------------
// Problem constants
// ---------------------------------------------------------------------------
#define DIM   384
#define NH    12
#define HD    32
#define WS    14
#define BATCH 16
#define HH    56
#define WW    56
#define NWIN  256
#define NTOK  196
#define TOK   50176          // NWIN*NTOK

// ---------------------------------------------------------------------------
// Scratch
// ---------------------------------------------------------------------------
__device__ __align__(16) float  g_X0 [(size_t)TOK * DIM];
__device__ __align__(16) __half g_Y  [(size_t)TOK * DIM];
__device__ __align__(16) __half g_QKV[(size_t)TOK * 3 * DIM];
__device__ __align__(16) __half g_ATT[(size_t)TOK * DIM];
__device__ __align__(16) float  g_X1 [(size_t)TOK * DIM];
__device__ __align__(16) __half g_F  [(size_t)TOK * 4 * DIM];
__device__ __align__(16) __half g_Wh [1769472];          // fp16 weights

#define N_QKV  (3 * DIM * DIM)
#define N_PROJ (DIM * DIM)
#define N_FC   (4 * DIM * DIM)
#define WOFF_QKV  0
#define WOFF_PROJ N_QKV
#define WOFF_FC1  (WOFF_PROJ + N_PROJ)
#define WOFF_FC2  (WOFF_FC1 + N_FC)

// ---------------------------------------------------------------------------
// helpers
// ---------------------------------------------------------------------------
__device__ __forceinline__ uint32_t smem_u32(const void* p) {
    uint32_t a;
    asm("{ .reg .u64 t; cvta.to.shared.u64 t, %1; cvt.u32.u64 %0, t; }" : "=r"(a) : "l"(p));
    return a;
}
__device__ __forceinline__ void cp16(uint32_t dst, const void* src) {
    asm volatile("cp.async.cg.shared.global [%0], [%1], 16;" :: "r"(dst), "l"(src));
}
#define CP_COMMIT() asm volatile("cp.async.commit_group;" ::: "memory")
#define CP_WAIT1()  asm volatile("cp.async.wait_group 1;" ::: "memory")

__device__ __forceinline__ void ldsm_x4(uint32_t* r, uint32_t a) {
    asm volatile("ldmatrix.sync.aligned.m8n8.x4.shared.b16 {%0,%1,%2,%3}, [%4];"
                 : "=r"(r[0]), "=r"(r[1]), "=r"(r[2]), "=r"(r[3]) : "r"(a));
}
__device__ __forceinline__ void ldsm_x4_t(uint32_t* r, uint32_t a) {
    asm volatile("ldmatrix.sync.aligned.m8n8.x4.trans.shared.b16 {%0,%1,%2,%3}, [%4];"
                 : "=r"(r[0]), "=r"(r[1]), "=r"(r[2]), "=r"(r[3]) : "r"(a));
}
__device__ __forceinline__ void mma_f16(float* d, const uint32_t* a, const uint32_t* b) {
    asm volatile(
        "mma.sync.aligned.m16n8k16.row.col.f32.f16.f16.f32 "
        "{%0,%1,%2,%3}, {%4,%5,%6,%7}, {%8,%9}, {%0,%1,%2,%3};"
        : "+f"(d[0]), "+f"(d[1]), "+f"(d[2]), "+f"(d[3])
        : "r"(a[0]), "r"(a[1]), "r"(a[2]), "r"(a[3]), "r"(b[0]), "r"(b[1]));
}
__device__ __forceinline__ uint32_t pack_h2(float x, float y) {
    __half2 h = __floats2half2_rn(x, y);
    return *reinterpret_cast<uint32_t*>(&h);
}
// token index m, channel c -> BCHW flat index
__device__ __forceinline__ int bchw_idx(int m, int c) {
    const int wi = m / NTOK;
    const int n  = m % NTOK;
    const int b  = wi >> 4;
    const int q  = wi & 15;
    const int h  = (q >> 2) * WS + n / WS;
    const int w  = (q & 3) * WS + n % WS;
    return ((b * DIM + c) * HH + h) * WW + w;
}

// ---------------------------------------------------------------------------
// 0) all four weight conversions in ONE launch
// ---------------------------------------------------------------------------
__global__ void cvtw_all_kernel(const float* __restrict__ qkv_w,
                                const float* __restrict__ proj_w,
                                const float* __restrict__ fc1_w,
                                const float* __restrict__ fc2_w,
                                __half* __restrict__ dst)
{
    int i = blockIdx.x * blockDim.x + threadIdx.x;
    if (i >= 1769472) return;
    float v;
    if (i < WOFF_PROJ)                v = qkv_w[i];
    else if (i < WOFF_FC1)            v = proj_w[i - WOFF_PROJ];
    else if (i < WOFF_FC2)            v = fc1_w[i - WOFF_FC1];
    else                              v = fc2_w[i - WOFF_FC2];
    dst[i] = __float2half_rn(v);
}

// ---------------------------------------------------------------------------
// 1) depthwise 3x3 conv PE + residual -> windowed (wi,n,c)
// ---------------------------------------------------------------------------
__global__ void conv_pe_kernel(const float* __restrict__ x,
                               const float* __restrict__ cw,
                               const float* __restrict__ cb,
                               float* __restrict__ X0)
{
    const int cg = blockIdx.x * 8;
    const int h0 = blockIdx.y * 4;
    const int b  = blockIdx.z;

    __shared__ float sm[8][6][58];

    const int tid = threadIdx.y * 8 + threadIdx.x;
    const int lc  = tid / 56;
    const int lw  = tid % 56;

    const float* xp = x + ((size_t)(b * DIM + cg + lc) * HH) * WW;
#pragma unroll
    for (int r = 0; r < 6; r++) {
        int hh = h0 - 1 + r;
        float v = (hh >= 0 && hh < HH) ? xp[hh * WW + lw] : 0.0f;
        sm[lc][r][lw + 1] = v;
        if (lw == 0)  sm[lc][r][0]  = 0.0f;
        if (lw == 55) sm[lc][r][57] = 0.0f;
    }
    __syncthreads();

    const int c = threadIdx.x;
    const int w = threadIdx.y;

    float wreg[9];
    const float* cwp = cw + (size_t)(cg + c) * 9;
#pragma unroll
    for (int i = 0; i < 9; i++) wreg[i] = cwp[i];
    const float cbv = cb[cg + c];

#pragma unroll
    for (int j = 0; j < 4; j++) {
        const int h = h0 + j;
        float pe = 0.0f;
#pragma unroll
        for (int kh = 0; kh < 3; kh++)
#pragma unroll
            for (int kw = 0; kw < 3; kw++)
                pe += wreg[kh * 3 + kw] * sm[c][j + kh][w + kw];

        const float val = sm[c][j + 1][w + 1] + pe + cbv;

        const int wi = (b * 4 + h / WS) * 4 + (w / WS);
        const int n  = (h % WS) * WS + (w % WS);
        X0[((size_t)wi * NTOK + n) * DIM + cg + c] = val;
    }
}

// ---------------------------------------------------------------------------
// 2) LayerNorm; fp16 output
// ---------------------------------------------------------------------------
__global__ void ln_kernel(const float* __restrict__ X,
                          const float* __restrict__ gamma,
                          const float* __restrict__ beta,
                          __half* __restrict__ Y)
{
    const int warp = (blockIdx.x * blockDim.x + threadIdx.x) >> 5;
    const int lane = threadIdx.x & 31;
    if (warp >= TOK) return;

    const float* xp = X + (size_t)warp * DIM;
    float v[12];
    float s = 0.0f;
#pragma unroll
    for (int k = 0; k < 12; k++) { v[k] = xp[lane + 32 * k]; s += v[k]; }
#pragma unroll
    for (int o = 16; o; o >>= 1) s += __shfl_xor_sync(0xffffffffu, s, o);
    const float mean = s * (1.0f / DIM);

    float q = 0.0f;
#pragma unroll
    for (int k = 0; k < 12; k++) { float d = v[k] - mean; q += d * d; }
#pragma unroll
    for (int o = 16; o; o >>= 1) q += __shfl_xor_sync(0xffffffffu, q, o);
    const float inv = rsqrtf(q * (1.0f / DIM) + 1e-5f);

    __half* yp = Y + (size_t)warp * DIM;
#pragma unroll
    for (int k = 0; k < 12; k++) {
        int c = lane + 32 * k;
        yp[c] = __float2half_rn((v[k] - mean) * inv * gamma[c] + beta[c]);
    }
}

// ---------------------------------------------------------------------------
// 3) FP16 mma.sync GEMM, compile-time shapes.  M = TOK always.
//    CTA 128x128, BK=64, 8 warps (2m x 4n), warp 64x32, 3-stage, occ 2.
//    OMODE: 0 = fp32 (+R), 1 = fp16, 2 = BCHW scatter (+R)
// ---------------------------------------------------------------------------
#define BM 128
#define BN 128
#define BK 64
#define ROW_B 144
#define A_BYTES (128 * ROW_B)
#define STAGE_B (2 * A_BYTES)
#define NSTAGE  3
#define GEMM_SMEM (NSTAGE * STAGE_B)

template<int N, int K, int ACT, int OMODE>
__global__ __launch_bounds__(256, 2)
void hgemm_kernel(const __half* __restrict__ A,
                  const __half* __restrict__ W,
                  const float* __restrict__ bias,
                  const float* __restrict__ R,
                  float* __restrict__ Cf,
                  __half* __restrict__ Ch)
{
    extern __shared__ char smc[];
    const uint32_t smem_base = smem_u32(smc);
    const int tid  = threadIdx.x;
    const int lane = tid & 31;
    const int wid  = tid >> 5;
    const int bm = blockIdx.y * BM;
    const int bn = blockIdx.x * BN;

    const int warp_m = (wid & 1) * 64;
    const int warp_n = (wid >> 1) * 32;

    float acc[4][4][4];
#pragma unroll
    for (int im = 0; im < 4; im++)
#pragma unroll
        for (int in = 0; in < 4; in++)
#pragma unroll
            for (int j = 0; j < 4; j++) acc[im][in][j] = 0.0f;

    const int g  = lane >> 3;
    const int r8 = lane & 7;
    const int a_row = warp_m + (g & 1) * 8 + r8;
    const int a_cg  = g >> 1;
    const int b_row = warp_n + (g >> 1) * 8 + r8;
    const int b_cg  = g & 1;

    constexpr int NC = K >> 6;

    const int fr  = tid >> 1;
    const int fc0 = (tid & 1) * 4;
    auto fill = [&](int kc, int st) {
        const int k0 = kc << 6;
        const uint32_t sb = smem_base + (uint32_t)st * STAGE_B;
        const __half* Ag = A + (size_t)(bm + fr) * K + k0;
        const __half* Wg = W + (size_t)(bn + fr) * K + k0;
#pragma unroll
        for (int c = 0; c < 4; c++) {
            const int cc = fc0 + c;
            const uint32_t so = (uint32_t)(fr * ROW_B + cc * 16);
            cp16(sb + so, Ag + cc * 8);
            cp16(sb + A_BYTES + so, Wg + cc * 8);
        }
    };

    fill(0, 0); CP_COMMIT();
    fill(1, 1); CP_COMMIT();

    for (int kc = 0; kc < NC; kc++) {
        CP_WAIT1();
        __syncthreads();

        if (kc + 2 < NC) fill(kc + 2, (kc + 2) % NSTAGE);
        CP_COMMIT();

        const uint32_t ab = smem_base + (uint32_t)(kc % NSTAGE) * STAGE_B;
        const uint32_t bb = ab + A_BYTES;

#pragma unroll
        for (int s = 0; s < 4; s++) {
            uint32_t af[4][4], bf[2][4];
#pragma unroll
            for (int im = 0; im < 4; im++)
                ldsm_x4(af[im], ab + (uint32_t)((a_row + im * 16) * ROW_B +
                                                (s * 2 + a_cg) * 16));
#pragma unroll
            for (int inp = 0; inp < 2; inp++)
                ldsm_x4(bf[inp], bb + (uint32_t)((b_row + inp * 16) * ROW_B +
                                                 (s * 2 + b_cg) * 16));
#pragma unroll
            for (int im = 0; im < 4; im++)
#pragma unroll
                for (int in = 0; in < 4; in++)
                    mma_f16(acc[im][in], af[im], &bf[in >> 1][(in & 1) * 2]);
        }
    }

    const int rq = lane >> 2;
    const int cq = (lane & 3) * 2;
#pragma unroll
    for (int im = 0; im < 4; im++) {
        const int row0 = bm + warp_m + im * 16 + rq;
#pragma unroll
        for (int in = 0; in < 4; in++) {
            const int col = bn + warp_n + in * 8 + cq;
            const float2 bv = *(const float2*)(bias + col);
            float v0 = acc[im][in][0] + bv.x;
            float v1 = acc[im][in][1] + bv.y;
            float v2 = acc[im][in][2] + bv.x;
            float v3 = acc[im][in][3] + bv.y;
            if (ACT == 1) {
                v0 = 0.5f * v0 * (1.0f + erff(v0 * 0.70710678118654752f));
                v1 = 0.5f * v1 * (1.0f + erff(v1 * 0.70710678118654752f));
                v2 = 0.5f * v2 * (1.0f + erff(v2 * 0.70710678118654752f));
                v3 = 0.5f * v3 * (1.0f + erff(v3 * 0.70710678118654752f));
            }
            if (OMODE == 1) {
                *(__half2*)(Ch + (size_t)row0 * N + col) =
                    __halves2half2(__float2half_rn(v0), __float2half_rn(v1));
                *(__half2*)(Ch + (size_t)(row0 + 8) * N + col) =
                    __halves2half2(__float2half_rn(v2), __float2half_rn(v3));
            } else {
                if (R) {
                    const float2 r0 = *(const float2*)(R + (size_t)row0 * N + col);
                    const float2 r1 = *(const float2*)(R + (size_t)(row0 + 8) * N + col);
                    v0 += r0.x; v1 += r0.y; v2 += r1.x; v3 += r1.y;
                }
                if (OMODE == 2) {
                    Cf[bchw_idx(row0,     col)]     = v0;
                    Cf[bchw_idx(row0,     col + 1)] = v1;
                    Cf[bchw_idx(row0 + 8, col)]     = v2;
                    Cf[bchw_idx(row0 + 8, col + 1)] = v3;
                } else {
                    *(float2*)(Cf + (size_t)row0 * N + col)       = make_float2(v0, v1);
                    *(float2*)(Cf + (size_t)(row0 + 8) * N + col) = make_float2(v2, v3);
                }
            }
        }
    }
}

// ---------------------------------------------------------------------------
// 4) Window attention: TWO heads per CTA (256 thr, 8 warps; warps 0-3 head A,
//    warps 4-7 head B; independent smem blocks). Online softmax, packed P
//    overwrites dead S registers (peak ~110 regs) -> occ 2 = 16 warps/SM.
// ---------------------------------------------------------------------------
#define AQ_STR 40
#define AROWS  208
#define HEAD_HALFS (3 * AROWS * AQ_STR)             // 24960 halfs per head
#define ATTN_SMEM (2 * HEAD_HALFS * 2)              // 99840 B

__global__ __launch_bounds__(256, 2)
void attn_h2_kernel(const __half* __restrict__ QKV, __half* __restrict__ ATT)
{
    const int wi = blockIdx.x / (NH / 2);
    const int hp = blockIdx.x % (NH / 2);

    extern __shared__ __half shh[];

    const int tid  = threadIdx.x;
    const int warp = tid >> 5;
    const int lane = tid & 31;
    const float scale = 0.1767766952966369f;   // 1/sqrt(32)

    // ---- load both heads' q/k/v slices ----
    const __half* wbase = QKV + (size_t)wi * NTOK * (3 * DIM);
    for (int idx = tid; idx < AROWS * 8; idx += 256) {
        const int hs  = (idx >= AROWS * 4) ? 1 : 0;
        const int rem = idx - hs * AROWS * 4;
        const int row = rem >> 2, c = rem & 3;
        __half* dh = shh + hs * HEAD_HALFS;
        uint4 q = make_uint4(0, 0, 0, 0), k = q, v = q;
        if (row < NTOK) {
            const __half* src = wbase + (size_t)row * (3 * DIM) + (hp * 2 + hs) * HD + c * 8;
            q = *(const uint4*)(src);
            k = *(const uint4*)(src + DIM);
            v = *(const uint4*)(src + 2 * DIM);
        }
        *(uint4*)(dh + row * AQ_STR + c * 8) = q;
        *(uint4*)(dh + AROWS * AQ_STR + row * AQ_STR + c * 8) = k;
        *(uint4*)(dh + 2 * AROWS * AQ_STR + row * AQ_STR + c * 8) = v;
    }
    __syncthreads();

    const int hsel = warp >> 2;               // 0 or 1
    const int hdi  = hp * 2 + hsel;
    const int wl   = warp & 3;

    const __half* hb = shh + hsel * HEAD_HALFS;
    const uint32_t qb = smem_u32(hb);
    const uint32_t kb = qb + AROWS * AQ_STR * 2;
    const uint32_t vb = kb + AROWS * AQ_STR * 2;

    const int g  = lane >> 3;
    const int r8 = lane & 7;
    const int a_row_off = (g & 1) * 8 + r8;
    const int a_cg      = (g >> 1) * 16;
    const int b_row_off = (g >> 1) * 8 + r8;
    const int b_cg      = (g & 1) * 16;

    const int rq  = lane >> 2;
    const int cq2 = (lane & 3) * 2;

    for (int t = wl; t < 13; t += 4) {
        const int m0 = t * 16;

        uint32_t af[2][4];
#pragma unroll
        for (int s = 0; s < 2; s++)
            ldsm_x4(af[s], qb + (uint32_t)((m0 + a_row_off) * 80 + a_cg + s * 32));

        float m0r = -1e30f, m1r = -1e30f;
        float s0 = 0.f, s1 = 0.f;
        float o[4][4];
#pragma unroll
        for (int n = 0; n < 4; n++) { o[n][0] = o[n][1] = o[n][2] = o[n][3] = 0.f; }

#pragma unroll
        for (int ch = 0; ch < 2; ch++) {
            const int NT    = ch ? 12 : 14;
            const int base8 = ch ? 112 : 0;

            // ---- S chunk ----
            float c[14][4];
#pragma unroll
            for (int nt = 0; nt < 14; nt++) { c[nt][0] = c[nt][1] = c[nt][2] = c[nt][3] = 0.f; }
#pragma unroll
            for (int np = 0; np < 7; np++) {
                if (np >= NT / 2) break;
#pragma unroll
                for (int s = 0; s < 2; s++) {
                    uint32_t bf[4];
                    ldsm_x4(bf, kb + (uint32_t)((base8 + np * 16 + b_row_off) * 80 + b_cg + s * 32));
                    mma_f16(c[2 * np],     af[s], &bf[0]);
                    mma_f16(c[2 * np + 1], af[s], &bf[2]);
                }
            }

            // ---- chunk max ----
            float mx0 = -1e30f, mx1 = -1e30f;
#pragma unroll
            for (int nt = 0; nt < 14; nt++) {
                if (nt >= NT) break;
                const int col = base8 + nt * 8 + cq2;
                const bool ok0 = (ch == 0) || (col < NTOK);
                const bool ok1 = (ch == 0) || (col + 1 < NTOK);
                if (ok0) { mx0 = fmaxf(mx0, c[nt][0]); mx1 = fmaxf(mx1, c[nt][2]); }
                if (ok1) { mx0 = fmaxf(mx0, c[nt][1]); mx1 = fmaxf(mx1, c[nt][3]); }
            }
            mx0 = fmaxf(mx0, __shfl_xor_sync(0xffffffffu, mx0, 1));
            mx0 = fmaxf(mx0, __shfl_xor_sync(0xffffffffu, mx0, 2));
            mx1 = fmaxf(mx1, __shfl_xor_sync(0xffffffffu, mx1, 1));
            mx1 = fmaxf(mx1, __shfl_xor_sync(0xffffffffu, mx1, 2));

            const float nm0 = fmaxf(m0r, mx0);
            const float nm1 = fmaxf(m1r, mx1);
            const float r0 = __expf((m0r - nm0) * scale);
            const float r1 = __expf((m1r - nm1) * scale);
            m0r = nm0; m1r = nm1;

            // ---- exp + pack IN PLACE (c[nt][0/1] <- packed halves) ----
            float cs0 = 0.f, cs1 = 0.f;
#pragma unroll
            for (int nt = 0; nt < 14; nt++) {
                if (nt >= NT) break;
                const int col = base8 + nt * 8 + cq2;
                const bool ok0 = (ch == 0) || (col < NTOK);
                const bool ok1 = (ch == 0) || (col + 1 < NTOK);
                float p0 = ok0 ? __expf((c[nt][0] - nm0) * scale) : 0.f;
                float p1 = ok1 ? __expf((c[nt][1] - nm0) * scale) : 0.f;
                float p2 = ok0 ? __expf((c[nt][2] - nm1) * scale) : 0.f;
                float p3 = ok1 ? __expf((c[nt][3] - nm1) * scale) : 0.f;
                cs0 += p0 + p1;
                cs1 += p2 + p3;
                c[nt][0] = __uint_as_float(pack_h2(p0, p1));
                c[nt][1] = __uint_as_float(pack_h2(p2, p3));
            }
            cs0 += __shfl_xor_sync(0xffffffffu, cs0, 1);
            cs0 += __shfl_xor_sync(0xffffffffu, cs0, 2);
            cs1 += __shfl_xor_sync(0xffffffffu, cs1, 1);
            cs1 += __shfl_xor_sync(0xffffffffu, cs1, 2);
            s0 = s0 * r0 + cs0;
            s1 = s1 * r1 + cs1;

#pragma unroll
            for (int n = 0; n < 4; n++) {
                o[n][0] *= r0; o[n][1] *= r0;
                o[n][2] *= r1; o[n][3] *= r1;
            }

            // ---- PV chunk (A from packed regs) ----
#pragma unroll
            for (int kt = 0; kt < 7; kt++) {
                if (kt >= NT / 2) break;
                uint32_t a[4] = { __float_as_uint(c[2 * kt][0]),
                                  __float_as_uint(c[2 * kt][1]),
                                  __float_as_uint(c[2 * kt + 1][0]),
                                  __float_as_uint(c[2 * kt + 1][1]) };
                uint32_t v0f[4], v1f[4];
                ldsm_x4_t(v0f, vb + (uint32_t)((base8 + kt * 16 + a_row_off) * 80 + a_cg));
                ldsm_x4_t(v1f, vb + (uint32_t)((base8 + kt * 16 + a_row_off) * 80 + a_cg + 32));
                mma_f16(o[0], a, &v0f[0]);
                mma_f16(o[1], a, &v0f[2]);
                mma_f16(o[2], a, &v1f[0]);
                mma_f16(o[3], a, &v1f[2]);
            }
        }

        // ---- normalize + store fp16 ----
        const float inv0 = 1.0f / s0;
        const float inv1 = 1.0f / s1;
        const int rr0 = m0 + rq, rr1 = m0 + rq + 8;
#pragma unroll
        for (int n = 0; n < 4; n++) {
            const int col = hdi * HD + n * 8 + cq2;
            if (rr0 < NTOK)
                *(__half2*)(ATT + ((size_t)wi * NTOK + rr0) * DIM + col) =
                    __halves2half2(__float2half_rn(o[n][0] * inv0), __float2half_rn(o[n][1] * inv0));
            if (rr1 < NTOK)
                *(__half2*)(ATT + ((size_t)wi * NTOK + rr1) * DIM + col) =
                    __halves2half2(__float2half_rn(o[n][2] * inv1), __float2half_rn(o[n][3] * inv1));
        }
    }
}

// ---------------------------------------------------------------------------
// Launch
// ---------------------------------------------------------------------------
extern "C" void kernel_launch(void* const* d_in, const int* in_sizes, int n_in,
                              void* d_out, int out_size)
{
    const float* x      = (const float*)d_in[0];
    const float* conv_w = (const float*)d_in[1];
    const float* conv_b = (const float*)d_in[2];
    const float* ln1_g  = (const float*)d_in[3];
    const float* ln1_b  = (const float*)d_in[4];
    const float* qkv_w  = (const float*)d_in[5];
    const float* qkv_b  = (const float*)d_in[6];
    const float* proj_w = (const float*)d_in[7];
    const float* proj_b = (const float*)d_in[8];
    const float* ln2_g  = (const float*)d_in[9];
    const float* ln2_b  = (const float*)d_in[10];
    const float* fc1_w  = (const float*)d_in[11];
    const float* fc1_b  = (const float*)d_in[12];
    const float* fc2_w  = (const float*)d_in[13];
    const float* fc2_b  = (const float*)d_in[14];
    float* out = (float*)d_out;

    float *X0, *X1;
    __half *Y, *QKV, *ATT, *F, *Wh;
    cudaGetSymbolAddress((void**)&X0,  g_X0);
    cudaGetSymbolAddress((void**)&Y,   g_Y);
    cudaGetSymbolAddress((void**)&QKV, g_QKV);
    cudaGetSymbolAddress((void**)&ATT, g_ATT);
    cudaGetSymbolAddress((void**)&X1,  g_X1);
    cudaGetSymbolAddress((void**)&F,   g_F);
    cudaGetSymbolAddress((void**)&Wh,  g_Wh);

    cudaFuncSetAttribute(attn_h2_kernel, cudaFuncAttributeMaxDynamicSharedMemorySize, ATTN_SMEM);
    cudaFuncSetAttribute(hgemm_kernel<1152, 384, 0, 1>, cudaFuncAttributeMaxDynamicSharedMemorySize, GEMM_SMEM);
    cudaFuncSetAttribute(hgemm_kernel<384, 384, 0, 0>,  cudaFuncAttributeMaxDynamicSharedMemorySize, GEMM_SMEM);
    cudaFuncSetAttribute(hgemm_kernel<1536, 384, 1, 1>, cudaFuncAttributeMaxDynamicSharedMemorySize, GEMM_SMEM);
    cudaFuncSetAttribute(hgemm_kernel<384, 1536, 0, 2>, cudaFuncAttributeMaxDynamicSharedMemorySize, GEMM_SMEM);

    // 0) fp16 weights
    cvtw_all_kernel<<<(1769472 + 255) / 256, 256>>>(qkv_w, proj_w, fc1_w, fc2_w, Wh);

    // 1) conv PE + residual -> X0
    conv_pe_kernel<<<dim3(DIM / 8, HH / 4, BATCH), dim3(8, 56)>>>(x, conv_w, conv_b, X0);

    // 2) LN1 -> Y (fp16)
    ln_kernel<<<TOK / 8, 256>>>(X0, ln1_g, ln1_b, Y);

    // 3) QKV GEMM
    hgemm_kernel<1152, 384, 0, 1><<<dim3(1152 / BN, TOK / BM), 256, GEMM_SMEM>>>(
        Y, Wh + WOFF_QKV, qkv_b, nullptr, nullptr, QKV);

    // 4) window attention (2 heads/CTA)
    attn_h2_kernel<<<NWIN * (NH / 2), 256, ATTN_SMEM>>>(QKV, ATT);

    // 5) proj GEMM + residual(X0) -> X1
    hgemm_kernel<384, 384, 0, 0><<<dim3(384 / BN, TOK / BM), 256, GEMM_SMEM>>>(
        ATT, Wh + WOFF_PROJ, proj_b, X0, X1, nullptr);

    // 6) LN2 -> Y (fp16)
    ln_kernel<<<TOK / 8, 256>>>(X1, ln2_g, ln2_b, Y);

    // 7) FC1 GEMM + GELU -> F (fp16)
    hgemm_kernel<1536, 384, 1, 1><<<dim3(1536 / BN, TOK / BM), 256, GEMM_SMEM>>>(
        Y, Wh + WOFF_FC1, fc1_b, nullptr, nullptr, F);

    // 8) FC2 GEMM + residual(X1) -> out (BCHW scatter)
    hgemm_kernel<384, 1536, 0, 2><<<dim3(384 / BN, TOK / BM), 256, GEMM_SMEM>>>(
        F, Wh + WOFF_FC2, fc2_b, X1, out, nullptr);
}

// round 14
// speedup vs baseline: 1.0731x; 1.0731x over previous
#include <cuda_runtime.h>
#include <cuda_bf16.h>
#include <cuda_fp16.h>
#include <math.h>
#include <cstdint>

// ---------------------------------------------------------------------------
// Problem constants
// ---------------------------------------------------------------------------
#define DIM   384
#define NH    12
#define HD    32
#define WS    14
#define BATCH 16
#define HH    56
#define WW    56
#define NWIN  256
#define NTOK  196
#define TOK   50176          // NWIN*NTOK

// ---------------------------------------------------------------------------
// Scratch
// ---------------------------------------------------------------------------
__device__ __align__(16) float  g_X0 [(size_t)TOK * DIM];
__device__ __align__(16) __half g_Y  [(size_t)TOK * DIM];
__device__ __align__(16) __half g_QKV[(size_t)TOK * 3 * DIM];
__device__ __align__(16) __half g_ATT[(size_t)TOK * DIM];
__device__ __align__(16) float  g_X1 [(size_t)TOK * DIM];
__device__ __align__(16) __half g_F  [(size_t)TOK * 4 * DIM];
__device__ __align__(16) __half g_Wh [1769472];          // fp16 weights

#define N_QKV  (3 * DIM * DIM)
#define N_PROJ (DIM * DIM)
#define N_FC   (4 * DIM * DIM)
#define WOFF_QKV  0
#define WOFF_PROJ N_QKV
#define WOFF_FC1  (WOFF_PROJ + N_PROJ)
#define WOFF_FC2  (WOFF_FC1 + N_FC)

// ---------------------------------------------------------------------------
// helpers
// ---------------------------------------------------------------------------
__device__ __forceinline__ uint32_t smem_u32(const void* p) {
    uint32_t a;
    asm("{ .reg .u64 t; cvta.to.shared.u64 t, %1; cvt.u32.u64 %0, t; }" : "=r"(a) : "l"(p));
    return a;
}
__device__ __forceinline__ void cp16(uint32_t dst, const void* src) {
    asm volatile("cp.async.cg.shared.global [%0], [%1], 16;" :: "r"(dst), "l"(src));
}
#define CP_COMMIT() asm volatile("cp.async.commit_group;" ::: "memory")
#define CP_WAIT1()  asm volatile("cp.async.wait_group 1;" ::: "memory")

__device__ __forceinline__ void ldsm_x4(uint32_t* r, uint32_t a) {
    asm volatile("ldmatrix.sync.aligned.m8n8.x4.shared.b16 {%0,%1,%2,%3}, [%4];"
                 : "=r"(r[0]), "=r"(r[1]), "=r"(r[2]), "=r"(r[3]) : "r"(a));
}
__device__ __forceinline__ void ldsm_x4_t(uint32_t* r, uint32_t a) {
    asm volatile("ldmatrix.sync.aligned.m8n8.x4.trans.shared.b16 {%0,%1,%2,%3}, [%4];"
                 : "=r"(r[0]), "=r"(r[1]), "=r"(r[2]), "=r"(r[3]) : "r"(a));
}
__device__ __forceinline__ void mma_f16(float* d, const uint32_t* a, const uint32_t* b) {
    asm volatile(
        "mma.sync.aligned.m16n8k16.row.col.f32.f16.f16.f32 "
        "{%0,%1,%2,%3}, {%4,%5,%6,%7}, {%8,%9}, {%0,%1,%2,%3};"
        : "+f"(d[0]), "+f"(d[1]), "+f"(d[2]), "+f"(d[3])
        : "r"(a[0]), "r"(a[1]), "r"(a[2]), "r"(a[3]), "r"(b[0]), "r"(b[1]));
}
__device__ __forceinline__ uint32_t pack_h2(float x, float y) {
    __half2 h = __floats2half2_rn(x, y);
    return *reinterpret_cast<uint32_t*>(&h);
}
// token index m, channel c -> BCHW flat index
__device__ __forceinline__ int bchw_idx(int m, int c) {
    const int wi = m / NTOK;
    const int n  = m % NTOK;
    const int b  = wi >> 4;
    const int q  = wi & 15;
    const int h  = (q >> 2) * WS + n / WS;
    const int w  = (q & 3) * WS + n % WS;
    return ((b * DIM + c) * HH + h) * WW + w;
}

// ---------------------------------------------------------------------------
// 0) all four weight conversions in ONE launch
// ---------------------------------------------------------------------------
__global__ void cvtw_all_kernel(const float* __restrict__ qkv_w,
                                const float* __restrict__ proj_w,
                                const float* __restrict__ fc1_w,
                                const float* __restrict__ fc2_w,
                                __half* __restrict__ dst)
{
    int i = blockIdx.x * blockDim.x + threadIdx.x;
    if (i >= 1769472) return;
    float v;
    if (i < WOFF_PROJ)                v = qkv_w[i];
    else if (i < WOFF_FC1)            v = proj_w[i - WOFF_PROJ];
    else if (i < WOFF_FC2)            v = fc1_w[i - WOFF_FC1];
    else                              v = fc2_w[i - WOFF_FC2];
    dst[i] = __float2half_rn(v);
}

// ---------------------------------------------------------------------------
// 1) depthwise 3x3 conv PE + residual -> windowed (wi,n,c)
// ---------------------------------------------------------------------------
__global__ void conv_pe_kernel(const float* __restrict__ x,
                               const float* __restrict__ cw,
                               const float* __restrict__ cb,
                               float* __restrict__ X0)
{
    const int cg = blockIdx.x * 8;
    const int h0 = blockIdx.y * 4;
    const int b  = blockIdx.z;

    __shared__ float sm[8][6][58];

    const int tid = threadIdx.y * 8 + threadIdx.x;
    const int lc  = tid / 56;
    const int lw  = tid % 56;

    const float* xp = x + ((size_t)(b * DIM + cg + lc) * HH) * WW;
#pragma unroll
    for (int r = 0; r < 6; r++) {
        int hh = h0 - 1 + r;
        float v = (hh >= 0 && hh < HH) ? xp[hh * WW + lw] : 0.0f;
        sm[lc][r][lw + 1] = v;
        if (lw == 0)  sm[lc][r][0]  = 0.0f;
        if (lw == 55) sm[lc][r][57] = 0.0f;
    }
    __syncthreads();

    const int c = threadIdx.x;
    const int w = threadIdx.y;

    float wreg[9];
    const float* cwp = cw + (size_t)(cg + c) * 9;
#pragma unroll
    for (int i = 0; i < 9; i++) wreg[i] = cwp[i];
    const float cbv = cb[cg + c];

#pragma unroll
    for (int j = 0; j < 4; j++) {
        const int h = h0 + j;
        float pe = 0.0f;
#pragma unroll
        for (int kh = 0; kh < 3; kh++)
#pragma unroll
            for (int kw = 0; kw < 3; kw++)
                pe += wreg[kh * 3 + kw] * sm[c][j + kh][w + kw];

        const float val = sm[c][j + 1][w + 1] + pe + cbv;

        const int wi = (b * 4 + h / WS) * 4 + (w / WS);
        const int n  = (h % WS) * WS + (w % WS);
        X0[((size_t)wi * NTOK + n) * DIM + cg + c] = val;
    }
}

// ---------------------------------------------------------------------------
// 2) LayerNorm; fp16 output
// ---------------------------------------------------------------------------
__global__ void ln_kernel(const float* __restrict__ X,
                          const float* __restrict__ gamma,
                          const float* __restrict__ beta,
                          __half* __restrict__ Y)
{
    const int warp = (blockIdx.x * blockDim.x + threadIdx.x) >> 5;
    const int lane = threadIdx.x & 31;
    if (warp >= TOK) return;

    const float* xp = X + (size_t)warp * DIM;
    float v[12];
    float s = 0.0f;
#pragma unroll
    for (int k = 0; k < 12; k++) { v[k] = xp[lane + 32 * k]; s += v[k]; }
#pragma unroll
    for (int o = 16; o; o >>= 1) s += __shfl_xor_sync(0xffffffffu, s, o);
    const float mean = s * (1.0f / DIM);

    float q = 0.0f;
#pragma unroll
    for (int k = 0; k < 12; k++) { float d = v[k] - mean; q += d * d; }
#pragma unroll
    for (int o = 16; o; o >>= 1) q += __shfl_xor_sync(0xffffffffu, q, o);
    const float inv = rsqrtf(q * (1.0f / DIM) + 1e-5f);

    __half* yp = Y + (size_t)warp * DIM;
#pragma unroll
    for (int k = 0; k < 12; k++) {
        int c = lane + 32 * k;
        yp[c] = __float2half_rn((v[k] - mean) * inv * gamma[c] + beta[c]);
    }
}

// ---------------------------------------------------------------------------
// 3) FP16 mma.sync GEMM, compile-time shapes, K-loop unrolled by 3 so the
//    pipeline stage index is a compile-time constant (no % NSTAGE in loop).
//    CTA 128x128, BK=64, 8 warps (2m x 4n), warp 64x32, 3-stage, occ 2.
//    OMODE: 0 = fp32 (+R), 1 = fp16, 2 = BCHW scatter (+R)
// ---------------------------------------------------------------------------
#define BM 128
#define BN 128
#define BK 64
#define ROW_B 144
#define A_BYTES (128 * ROW_B)
#define STAGE_B (2 * A_BYTES)
#define NSTAGE  3
#define GEMM_SMEM (NSTAGE * STAGE_B)

template<int N, int K, int ACT, int OMODE>
__global__ __launch_bounds__(256, 2)
void hgemm_kernel(const __half* __restrict__ A,
                  const __half* __restrict__ W,
                  const float* __restrict__ bias,
                  const float* __restrict__ R,
                  float* __restrict__ Cf,
                  __half* __restrict__ Ch)
{
    extern __shared__ char smc[];
    const uint32_t smem_base = smem_u32(smc);
    const int tid  = threadIdx.x;
    const int lane = tid & 31;
    const int wid  = tid >> 5;
    const int bm = blockIdx.y * BM;
    const int bn = blockIdx.x * BN;

    const int warp_m = (wid & 1) * 64;
    const int warp_n = (wid >> 1) * 32;

    float acc[4][4][4];
#pragma unroll
    for (int im = 0; im < 4; im++)
#pragma unroll
        for (int in = 0; in < 4; in++)
#pragma unroll
            for (int j = 0; j < 4; j++) acc[im][in][j] = 0.0f;

    const int g  = lane >> 3;
    const int r8 = lane & 7;
    const int a_row = warp_m + (g & 1) * 8 + r8;
    const int a_cg  = g >> 1;
    const int b_row = warp_n + (g >> 1) * 8 + r8;
    const int b_cg  = g & 1;

    constexpr int NC = K >> 6;          // 6 or 24: divisible by 3
    static_assert(NC % 3 == 0, "NC must be divisible by NSTAGE");

    const int fr  = tid >> 1;
    const int fc0 = (tid & 1) * 4;
    auto fill = [&](int kc, int st) {
        const int k0 = kc << 6;
        const uint32_t sb = smem_base + (uint32_t)st * STAGE_B;
        const __half* Ag = A + (size_t)(bm + fr) * K + k0;
        const __half* Wg = W + (size_t)(bn + fr) * K + k0;
#pragma unroll
        for (int c = 0; c < 4; c++) {
            const int cc = fc0 + c;
            const uint32_t so = (uint32_t)(fr * ROW_B + cc * 16);
            cp16(sb + so, Ag + cc * 8);
            cp16(sb + A_BYTES + so, Wg + cc * 8);
        }
    };

    auto mma_stage = [&](int st) {
        const uint32_t ab = smem_base + (uint32_t)st * STAGE_B;
        const uint32_t bb = ab + A_BYTES;
#pragma unroll
        for (int s = 0; s < 4; s++) {
            uint32_t af[4][4], bf[2][4];
#pragma unroll
            for (int im = 0; im < 4; im++)
                ldsm_x4(af[im], ab + (uint32_t)((a_row + im * 16) * ROW_B +
                                                (s * 2 + a_cg) * 16));
#pragma unroll
            for (int inp = 0; inp < 2; inp++)
                ldsm_x4(bf[inp], bb + (uint32_t)((b_row + inp * 16) * ROW_B +
                                                 (s * 2 + b_cg) * 16));
#pragma unroll
            for (int im = 0; im < 4; im++)
#pragma unroll
                for (int in = 0; in < 4; in++)
                    mma_f16(acc[im][in], af[im], &bf[in >> 1][(in & 1) * 2]);
        }
    };

    fill(0, 0); CP_COMMIT();
    fill(1, 1); CP_COMMIT();

    // unrolled-by-3 main loop: stage index compile-time constant per body
    for (int kb = 0; kb < NC; kb += 3) {
#pragma unroll
        for (int u = 0; u < 3; u++) {
            const int kc = kb + u;
            CP_WAIT1();
            __syncthreads();
            if (kc + 2 < NC) fill(kc + 2, (u + 2) % 3);
            CP_COMMIT();
            mma_stage(u);
        }
    }

    const int rq = lane >> 2;
    const int cq = (lane & 3) * 2;
#pragma unroll
    for (int im = 0; im < 4; im++) {
        const int row0 = bm + warp_m + im * 16 + rq;
#pragma unroll
        for (int in = 0; in < 4; in++) {
            const int col = bn + warp_n + in * 8 + cq;
            const float2 bv = *(const float2*)(bias + col);
            float v0 = acc[im][in][0] + bv.x;
            float v1 = acc[im][in][1] + bv.y;
            float v2 = acc[im][in][2] + bv.x;
            float v3 = acc[im][in][3] + bv.y;
            if (ACT == 1) {
                v0 = 0.5f * v0 * (1.0f + erff(v0 * 0.70710678118654752f));
                v1 = 0.5f * v1 * (1.0f + erff(v1 * 0.70710678118654752f));
                v2 = 0.5f * v2 * (1.0f + erff(v2 * 0.70710678118654752f));
                v3 = 0.5f * v3 * (1.0f + erff(v3 * 0.70710678118654752f));
            }
            if (OMODE == 1) {
                *(__half2*)(Ch + (size_t)row0 * N + col) =
                    __halves2half2(__float2half_rn(v0), __float2half_rn(v1));
                *(__half2*)(Ch + (size_t)(row0 + 8) * N + col) =
                    __halves2half2(__float2half_rn(v2), __float2half_rn(v3));
            } else {
                if (R) {
                    const float2 r0 = *(const float2*)(R + (size_t)row0 * N + col);
                    const float2 r1 = *(const float2*)(R + (size_t)(row0 + 8) * N + col);
                    v0 += r0.x; v1 += r0.y; v2 += r1.x; v3 += r1.y;
                }
                if (OMODE == 2) {
                    Cf[bchw_idx(row0,     col)]     = v0;
                    Cf[bchw_idx(row0,     col + 1)] = v1;
                    Cf[bchw_idx(row0 + 8, col)]     = v2;
                    Cf[bchw_idx(row0 + 8, col + 1)] = v3;
                } else {
                    *(float2*)(Cf + (size_t)row0 * N + col)       = make_float2(v0, v1);
                    *(float2*)(Cf + (size_t)(row0 + 8) * N + col) = make_float2(v2, v3);
                }
            }
        }
    }
}

// ---------------------------------------------------------------------------
// 4) Window attention (R12 best version): fp16 mma, online softmax 2 chunks,
//    1 head per CTA, 128 threads, occupancy 3.
// ---------------------------------------------------------------------------
#define AQ_STR 40
#define AROWS  208
#define ATTN_SMEM (3 * AROWS * AQ_STR * 2)      // 49920 B

__global__ __launch_bounds__(128, 3)
void attn_h_kernel(const __half* __restrict__ QKV, __half* __restrict__ ATT)
{
    const int wi  = blockIdx.x / NH;
    const int hdi = blockIdx.x % NH;

    extern __shared__ __half shh[];
    __half* qs = shh;
    __half* ks = qs + AROWS * AQ_STR;
    __half* vs = ks + AROWS * AQ_STR;

    const int tid  = threadIdx.x;
    const int warp = tid >> 5;
    const int lane = tid & 31;
    const float scale = 0.1767766952966369f;   // 1/sqrt(32)

    const __half* base = QKV + (size_t)wi * NTOK * (3 * DIM) + hdi * HD;
    for (int idx = tid; idx < AROWS * 4; idx += 128) {
        const int row = idx >> 2, c = idx & 3;
        uint4 q = make_uint4(0, 0, 0, 0), k = q, v = q;
        if (row < NTOK) {
            const __half* src = base + (size_t)row * (3 * DIM) + c * 8;
            q = *(const uint4*)(src);
            k = *(const uint4*)(src + DIM);
            v = *(const uint4*)(src + 2 * DIM);
        }
        *(uint4*)(qs + row * AQ_STR + c * 8) = q;
        *(uint4*)(ks + row * AQ_STR + c * 8) = k;
        *(uint4*)(vs + row * AQ_STR + c * 8) = v;
    }
    __syncthreads();

    const uint32_t qb = smem_u32(qs);
    const uint32_t kb = smem_u32(ks);
    const uint32_t vb = smem_u32(vs);

    const int g  = lane >> 3;
    const int r8 = lane & 7;
    const int a_row_off = (g & 1) * 8 + r8;
    const int a_cg      = (g >> 1) * 16;
    const int b_row_off = (g >> 1) * 8 + r8;
    const int b_cg      = (g & 1) * 16;

    const int rq  = lane >> 2;
    const int cq2 = (lane & 3) * 2;

    for (int t = warp; t < 13; t += 4) {
        const int m0 = t * 16;

        uint32_t af[2][4];
#pragma unroll
        for (int s = 0; s < 2; s++)
            ldsm_x4(af[s], qb + (uint32_t)((m0 + a_row_off) * 80 + a_cg + s * 32));

        float m0r = -1e30f, m1r = -1e30f;
        float s0 = 0.f, s1 = 0.f;
        float o[4][4];
#pragma unroll
        for (int n = 0; n < 4; n++) { o[n][0] = o[n][1] = o[n][2] = o[n][3] = 0.f; }

#pragma unroll
        for (int ch = 0; ch < 2; ch++) {
            const int NT    = ch ? 12 : 14;
            const int base8 = ch ? 112 : 0;

            float c[14][4];
#pragma unroll
            for (int nt = 0; nt < 14; nt++) { c[nt][0] = c[nt][1] = c[nt][2] = c[nt][3] = 0.f; }
#pragma unroll
            for (int np = 0; np < 7; np++) {
                if (np >= NT / 2) break;
#pragma unroll
                for (int s = 0; s < 2; s++) {
                    uint32_t bf[4];
                    ldsm_x4(bf, kb + (uint32_t)((base8 + np * 16 + b_row_off) * 80 + b_cg + s * 32));
                    mma_f16(c[2 * np],     af[s], &bf[0]);
                    mma_f16(c[2 * np + 1], af[s], &bf[2]);
                }
            }

            float mx0 = -1e30f, mx1 = -1e30f;
#pragma unroll
            for (int nt = 0; nt < 14; nt++) {
                if (nt >= NT) break;
                const int col = base8 + nt * 8 + cq2;
                const bool ok0 = (ch == 0) || (col < NTOK);
                const bool ok1 = (ch == 0) || (col + 1 < NTOK);
                if (ok0) { mx0 = fmaxf(mx0, c[nt][0]); mx1 = fmaxf(mx1, c[nt][2]); }
                if (ok1) { mx0 = fmaxf(mx0, c[nt][1]); mx1 = fmaxf(mx1, c[nt][3]); }
            }
            mx0 = fmaxf(mx0, __shfl_xor_sync(0xffffffffu, mx0, 1));
            mx0 = fmaxf(mx0, __shfl_xor_sync(0xffffffffu, mx0, 2));
            mx1 = fmaxf(mx1, __shfl_xor_sync(0xffffffffu, mx1, 1));
            mx1 = fmaxf(mx1, __shfl_xor_sync(0xffffffffu, mx1, 2));

            const float nm0 = fmaxf(m0r, mx0);
            const float nm1 = fmaxf(m1r, mx1);
            const float r0 = __expf((m0r - nm0) * scale);
            const float r1 = __expf((m1r - nm1) * scale);
            m0r = nm0; m1r = nm1;

            uint32_t ph[14][2];
            float cs0 = 0.f, cs1 = 0.f;
#pragma unroll
            for (int nt = 0; nt < 14; nt++) {
                if (nt >= NT) break;
                const int col = base8 + nt * 8 + cq2;
                const bool ok0 = (ch == 0) || (col < NTOK);
                const bool ok1 = (ch == 0) || (col + 1 < NTOK);
                float p0 = ok0 ? __expf((c[nt][0] - nm0) * scale) : 0.f;
                float p1 = ok1 ? __expf((c[nt][1] - nm0) * scale) : 0.f;
                float p2 = ok0 ? __expf((c[nt][2] - nm1) * scale) : 0.f;
                float p3 = ok1 ? __expf((c[nt][3] - nm1) * scale) : 0.f;
                cs0 += p0 + p1;
                cs1 += p2 + p3;
                ph[nt][0] = pack_h2(p0, p1);
                ph[nt][1] = pack_h2(p2, p3);
            }
            cs0 += __shfl_xor_sync(0xffffffffu, cs0, 1);
            cs0 += __shfl_xor_sync(0xffffffffu, cs0, 2);
            cs1 += __shfl_xor_sync(0xffffffffu, cs1, 1);
            cs1 += __shfl_xor_sync(0xffffffffu, cs1, 2);
            s0 = s0 * r0 + cs0;
            s1 = s1 * r1 + cs1;

#pragma unroll
            for (int n = 0; n < 4; n++) {
                o[n][0] *= r0; o[n][1] *= r0;
                o[n][2] *= r1; o[n][3] *= r1;
            }

#pragma unroll
            for (int kt = 0; kt < 7; kt++) {
                if (kt >= NT / 2) break;
                uint32_t a[4] = { ph[2 * kt][0], ph[2 * kt][1],
                                  ph[2 * kt + 1][0], ph[2 * kt + 1][1] };
                uint32_t v0f[4], v1f[4];
                ldsm_x4_t(v0f, vb + (uint32_t)((base8 + kt * 16 + a_row_off) * 80 + a_cg));
                ldsm_x4_t(v1f, vb + (uint32_t)((base8 + kt * 16 + a_row_off) * 80 + a_cg + 32));
                mma_f16(o[0], a, &v0f[0]);
                mma_f16(o[1], a, &v0f[2]);
                mma_f16(o[2], a, &v1f[0]);
                mma_f16(o[3], a, &v1f[2]);
            }
        }

        const float inv0 = 1.0f / s0;
        const float inv1 = 1.0f / s1;
        const int rr0 = m0 + rq, rr1 = m0 + rq + 8;
#pragma unroll
        for (int n = 0; n < 4; n++) {
            const int col = hdi * HD + n * 8 + cq2;
            if (rr0 < NTOK)
                *(__half2*)(ATT + ((size_t)wi * NTOK + rr0) * DIM + col) =
                    __halves2half2(__float2half_rn(o[n][0] * inv0), __float2half_rn(o[n][1] * inv0));
            if (rr1 < NTOK)
                *(__half2*)(ATT + ((size_t)wi * NTOK + rr1) * DIM + col) =
                    __halves2half2(__float2half_rn(o[n][2] * inv1), __float2half_rn(o[n][3] * inv1));
        }
    }
}

// ---------------------------------------------------------------------------
// Launch
// ---------------------------------------------------------------------------
extern "C" void kernel_launch(void* const* d_in, const int* in_sizes, int n_in,
                              void* d_out, int out_size)
{
    const float* x      = (const float*)d_in[0];
    const float* conv_w = (const float*)d_in[1];
    const float* conv_b = (const float*)d_in[2];
    const float* ln1_g  = (const float*)d_in[3];
    const float* ln1_b  = (const float*)d_in[4];
    const float* qkv_w  = (const float*)d_in[5];
    const float* qkv_b  = (const float*)d_in[6];
    const float* proj_w = (const float*)d_in[7];
    const float* proj_b = (const float*)d_in[8];
    const float* ln2_g  = (const float*)d_in[9];
    const float* ln2_b  = (const float*)d_in[10];
    const float* fc1_w  = (const float*)d_in[11];
    const float* fc1_b  = (const float*)d_in[12];
    const float* fc2_w  = (const float*)d_in[13];
    const float* fc2_b  = (const float*)d_in[14];
    float* out = (float*)d_out;

    float *X0, *X1;
    __half *Y, *QKV, *ATT, *F, *Wh;
    cudaGetSymbolAddress((void**)&X0,  g_X0);
    cudaGetSymbolAddress((void**)&Y,   g_Y);
    cudaGetSymbolAddress((void**)&QKV, g_QKV);
    cudaGetSymbolAddress((void**)&ATT, g_ATT);
    cudaGetSymbolAddress((void**)&X1,  g_X1);
    cudaGetSymbolAddress((void**)&F,   g_F);
    cudaGetSymbolAddress((void**)&Wh,  g_Wh);

    cudaFuncSetAttribute(attn_h_kernel, cudaFuncAttributeMaxDynamicSharedMemorySize, ATTN_SMEM);
    cudaFuncSetAttribute(hgemm_kernel<1152, 384, 0, 1>, cudaFuncAttributeMaxDynamicSharedMemorySize, GEMM_SMEM);
    cudaFuncSetAttribute(hgemm_kernel<384, 384, 0, 0>,  cudaFuncAttributeMaxDynamicSharedMemorySize, GEMM_SMEM);
    cudaFuncSetAttribute(hgemm_kernel<1536, 384, 1, 1>, cudaFuncAttributeMaxDynamicSharedMemorySize, GEMM_SMEM);
    cudaFuncSetAttribute(hgemm_kernel<384, 1536, 0, 2>, cudaFuncAttributeMaxDynamicSharedMemorySize, GEMM_SMEM);

    // 0) fp16 weights
    cvtw_all_kernel<<<(1769472 + 255) / 256, 256>>>(qkv_w, proj_w, fc1_w, fc2_w, Wh);

    // 1) conv PE + residual -> X0
    conv_pe_kernel<<<dim3(DIM / 8, HH / 4, BATCH), dim3(8, 56)>>>(x, conv_w, conv_b, X0);

    // 2) LN1 -> Y (fp16)
    ln_kernel<<<TOK / 8, 256>>>(X0, ln1_g, ln1_b, Y);

    // 3) QKV GEMM
    hgemm_kernel<1152, 384, 0, 1><<<dim3(1152 / BN, TOK / BM), 256, GEMM_SMEM>>>(
        Y, Wh + WOFF_QKV, qkv_b, nullptr, nullptr, QKV);

    // 4) window attention (1 head/CTA, occ 3)
    attn_h_kernel<<<NWIN * NH, 128, ATTN_SMEM>>>(QKV, ATT);

    // 5) proj GEMM + residual(X0) -> X1
    hgemm_kernel<384, 384, 0, 0><<<dim3(384 / BN, TOK / BM), 256, GEMM_SMEM>>>(
        ATT, Wh + WOFF_PROJ, proj_b, X0, X1, nullptr);

    // 6) LN2 -> Y (fp16)
    ln_kernel<<<TOK / 8, 256>>>(X1, ln2_g, ln2_b, Y);

    // 7) FC1 GEMM + GELU -> F (fp16)
    hgemm_kernel<1536, 384, 1, 1><<<dim3(1536 / BN, TOK / BM), 256, GEMM_SMEM>>>(
        Y, Wh + WOFF_FC1, fc1_b, nullptr, nullptr, F);

    // 8) FC2 GEMM + residual(X1) -> out (BCHW scatter)
    hgemm_kernel<384, 1536, 0, 2><<<dim3(384 / BN, TOK / BM), 256, GEMM_SMEM>>>(
        F, Wh + WOFF_FC2, fc2_b, X1, out, nullptr);
}

// round 15
// speedup vs baseline: 1.0735x; 1.0004x over previous
#include <cuda_runtime.h>
#include <cuda_bf16.h>
#include <cuda_fp16.h>
#include <math.h>
#include <cstdint>

// ---------------------------------------------------------------------------
// Problem constants
// ---------------------------------------------------------------------------
#define DIM   384
#define NH    12
#define HD    32
#define WS    14
#define BATCH 16
#define HH    56
#define WW    56
#define NWIN  256
#define NTOK  196
#define TOK   50176          // NWIN*NTOK

// ---------------------------------------------------------------------------
// Scratch
// ---------------------------------------------------------------------------
__device__ __align__(16) float  g_X0 [(size_t)TOK * DIM];
__device__ __align__(16) __half g_Y  [(size_t)TOK * DIM];
__device__ __align__(16) __half g_QKV[(size_t)TOK * 3 * DIM];
__device__ __align__(16) __half g_ATT[(size_t)TOK * DIM];
__device__ __align__(16) float  g_X1 [(size_t)TOK * DIM];
__device__ __align__(16) __half g_F  [(size_t)TOK * 4 * DIM];
__device__ __align__(16) __half g_Wh [1769472];          // fp16 weights

#define N_QKV  (3 * DIM * DIM)
#define N_PROJ (DIM * DIM)
#define N_FC   (4 * DIM * DIM)
#define WOFF_QKV  0
#define WOFF_PROJ N_QKV
#define WOFF_FC1  (WOFF_PROJ + N_PROJ)
#define WOFF_FC2  (WOFF_FC1 + N_FC)

// ---------------------------------------------------------------------------
// helpers
// ---------------------------------------------------------------------------
__device__ __forceinline__ uint32_t smem_u32(const void* p) {
    uint32_t a;
    asm("{ .reg .u64 t; cvta.to.shared.u64 t, %1; cvt.u32.u64 %0, t; }" : "=r"(a) : "l"(p));
    return a;
}
__device__ __forceinline__ void cp16(uint32_t dst, const void* src) {
    asm volatile("cp.async.cg.shared.global [%0], [%1], 16;" :: "r"(dst), "l"(src));
}
#define CP_COMMIT() asm volatile("cp.async.commit_group;" ::: "memory")
#define CP_WAIT1()  asm volatile("cp.async.wait_group 1;" ::: "memory")

__device__ __forceinline__ void ldsm_x4(uint32_t* r, uint32_t a) {
    asm volatile("ldmatrix.sync.aligned.m8n8.x4.shared.b16 {%0,%1,%2,%3}, [%4];"
                 : "=r"(r[0]), "=r"(r[1]), "=r"(r[2]), "=r"(r[3]) : "r"(a));
}
__device__ __forceinline__ void ldsm_x4_t(uint32_t* r, uint32_t a) {
    asm volatile("ldmatrix.sync.aligned.m8n8.x4.trans.shared.b16 {%0,%1,%2,%3}, [%4];"
                 : "=r"(r[0]), "=r"(r[1]), "=r"(r[2]), "=r"(r[3]) : "r"(a));
}
__device__ __forceinline__ void mma_f16(float* d, const uint32_t* a, const uint32_t* b) {
    asm volatile(
        "mma.sync.aligned.m16n8k16.row.col.f32.f16.f16.f32 "
        "{%0,%1,%2,%3}, {%4,%5,%6,%7}, {%8,%9}, {%0,%1,%2,%3};"
        : "+f"(d[0]), "+f"(d[1]), "+f"(d[2]), "+f"(d[3])
        : "r"(a[0]), "r"(a[1]), "r"(a[2]), "r"(a[3]), "r"(b[0]), "r"(b[1]));
}
__device__ __forceinline__ uint32_t pack_h2(float x, float y) {
    __half2 h = __floats2half2_rn(x, y);
    return *reinterpret_cast<uint32_t*>(&h);
}
// token index m, channel c -> BCHW flat index
__device__ __forceinline__ int bchw_idx(int m, int c) {
    const int wi = m / NTOK;
    const int n  = m % NTOK;
    const int b  = wi >> 4;
    const int q  = wi & 15;
    const int h  = (q >> 2) * WS + n / WS;
    const int w  = (q & 3) * WS + n % WS;
    return ((b * DIM + c) * HH + h) * WW + w;
}

// ---------------------------------------------------------------------------
// 0) all four weight conversions in ONE launch
// ---------------------------------------------------------------------------
__global__ void cvtw_all_kernel(const float* __restrict__ qkv_w,
                                const float* __restrict__ proj_w,
                                const float* __restrict__ fc1_w,
                                const float* __restrict__ fc2_w,
                                __half* __restrict__ dst)
{
    int i = blockIdx.x * blockDim.x + threadIdx.x;
    if (i >= 1769472) return;
    float v;
    if (i < WOFF_PROJ)                v = qkv_w[i];
    else if (i < WOFF_FC1)            v = proj_w[i - WOFF_PROJ];
    else if (i < WOFF_FC2)            v = fc1_w[i - WOFF_FC1];
    else                              v = fc2_w[i - WOFF_FC2];
    dst[i] = __float2half_rn(v);
}

// ---------------------------------------------------------------------------
// 1) depthwise 3x3 conv PE + residual -> windowed (wi,n,c)
// ---------------------------------------------------------------------------
__global__ void conv_pe_kernel(const float* __restrict__ x,
                               const float* __restrict__ cw,
                               const float* __restrict__ cb,
                               float* __restrict__ X0)
{
    const int cg = blockIdx.x * 8;
    const int h0 = blockIdx.y * 4;
    const int b  = blockIdx.z;

    __shared__ float sm[8][6][58];

    const int tid = threadIdx.y * 8 + threadIdx.x;
    const int lc  = tid / 56;
    const int lw  = tid % 56;

    const float* xp = x + ((size_t)(b * DIM + cg + lc) * HH) * WW;
#pragma unroll
    for (int r = 0; r < 6; r++) {
        int hh = h0 - 1 + r;
        float v = (hh >= 0 && hh < HH) ? xp[hh * WW + lw] : 0.0f;
        sm[lc][r][lw + 1] = v;
        if (lw == 0)  sm[lc][r][0]  = 0.0f;
        if (lw == 55) sm[lc][r][57] = 0.0f;
    }
    __syncthreads();

    const int c = threadIdx.x;
    const int w = threadIdx.y;

    float wreg[9];
    const float* cwp = cw + (size_t)(cg + c) * 9;
#pragma unroll
    for (int i = 0; i < 9; i++) wreg[i] = cwp[i];
    const float cbv = cb[cg + c];

#pragma unroll
    for (int j = 0; j < 4; j++) {
        const int h = h0 + j;
        float pe = 0.0f;
#pragma unroll
        for (int kh = 0; kh < 3; kh++)
#pragma unroll
            for (int kw = 0; kw < 3; kw++)
                pe += wreg[kh * 3 + kw] * sm[c][j + kh][w + kw];

        const float val = sm[c][j + 1][w + 1] + pe + cbv;

        const int wi = (b * 4 + h / WS) * 4 + (w / WS);
        const int n  = (h % WS) * WS + (w % WS);
        X0[((size_t)wi * NTOK + n) * DIM + cg + c] = val;
    }
}

// ---------------------------------------------------------------------------
// 2) LayerNorm; fp16 output
// ---------------------------------------------------------------------------
__global__ void ln_kernel(const float* __restrict__ X,
                          const float* __restrict__ gamma,
                          const float* __restrict__ beta,
                          __half* __restrict__ Y)
{
    const int warp = (blockIdx.x * blockDim.x + threadIdx.x) >> 5;
    const int lane = threadIdx.x & 31;
    if (warp >= TOK) return;

    const float* xp = X + (size_t)warp * DIM;
    float v[12];
    float s = 0.0f;
#pragma unroll
    for (int k = 0; k < 12; k++) { v[k] = xp[lane + 32 * k]; s += v[k]; }
#pragma unroll
    for (int o = 16; o; o >>= 1) s += __shfl_xor_sync(0xffffffffu, s, o);
    const float mean = s * (1.0f / DIM);

    float q = 0.0f;
#pragma unroll
    for (int k = 0; k < 12; k++) { float d = v[k] - mean; q += d * d; }
#pragma unroll
    for (int o = 16; o; o >>= 1) q += __shfl_xor_sync(0xffffffffu, q, o);
    const float inv = rsqrtf(q * (1.0f / DIM) + 1e-5f);

    __half* yp = Y + (size_t)warp * DIM;
#pragma unroll
    for (int k = 0; k < 12; k++) {
        int c = lane + 32 * k;
        yp[c] = __float2half_rn((v[k] - mean) * inv * gamma[c] + beta[c]);
    }
}

// ---------------------------------------------------------------------------
// 3) FP16 mma.sync GEMM, compile-time shapes, K-loop unrolled by 3. [frozen]
//    CTA 128x128, BK=64, 8 warps (2m x 4n), warp 64x32, 3-stage, occ 2.
//    OMODE: 0 = fp32 (+R), 1 = fp16, 2 = BCHW scatter (+R)
// ---------------------------------------------------------------------------
#define BM 128
#define BN 128
#define BK 64
#define ROW_B 144
#define A_BYTES (128 * ROW_B)
#define STAGE_B (2 * A_BYTES)
#define NSTAGE  3
#define GEMM_SMEM (NSTAGE * STAGE_B)

template<int N, int K, int ACT, int OMODE>
__global__ __launch_bounds__(256, 2)
void hgemm_kernel(const __half* __restrict__ A,
                  const __half* __restrict__ W,
                  const float* __restrict__ bias,
                  const float* __restrict__ R,
                  float* __restrict__ Cf,
                  __half* __restrict__ Ch)
{
    extern __shared__ char smc[];
    const uint32_t smem_base = smem_u32(smc);
    const int tid  = threadIdx.x;
    const int lane = tid & 31;
    const int wid  = tid >> 5;
    const int bm = blockIdx.y * BM;
    const int bn = blockIdx.x * BN;

    const int warp_m = (wid & 1) * 64;
    const int warp_n = (wid >> 1) * 32;

    float acc[4][4][4];
#pragma unroll
    for (int im = 0; im < 4; im++)
#pragma unroll
        for (int in = 0; in < 4; in++)
#pragma unroll
            for (int j = 0; j < 4; j++) acc[im][in][j] = 0.0f;

    const int g  = lane >> 3;
    const int r8 = lane & 7;
    const int a_row = warp_m + (g & 1) * 8 + r8;
    const int a_cg  = g >> 1;
    const int b_row = warp_n + (g >> 1) * 8 + r8;
    const int b_cg  = g & 1;

    constexpr int NC = K >> 6;
    static_assert(NC % 3 == 0, "NC must be divisible by NSTAGE");

    const int fr  = tid >> 1;
    const int fc0 = (tid & 1) * 4;
    auto fill = [&](int kc, int st) {
        const int k0 = kc << 6;
        const uint32_t sb = smem_base + (uint32_t)st * STAGE_B;
        const __half* Ag = A + (size_t)(bm + fr) * K + k0;
        const __half* Wg = W + (size_t)(bn + fr) * K + k0;
#pragma unroll
        for (int c = 0; c < 4; c++) {
            const int cc = fc0 + c;
            const uint32_t so = (uint32_t)(fr * ROW_B + cc * 16);
            cp16(sb + so, Ag + cc * 8);
            cp16(sb + A_BYTES + so, Wg + cc * 8);
        }
    };

    auto mma_stage = [&](int st) {
        const uint32_t ab = smem_base + (uint32_t)st * STAGE_B;
        const uint32_t bb = ab + A_BYTES;
#pragma unroll
        for (int s = 0; s < 4; s++) {
            uint32_t af[4][4], bf[2][4];
#pragma unroll
            for (int im = 0; im < 4; im++)
                ldsm_x4(af[im], ab + (uint32_t)((a_row + im * 16) * ROW_B +
                                                (s * 2 + a_cg) * 16));
#pragma unroll
            for (int inp = 0; inp < 2; inp++)
                ldsm_x4(bf[inp], bb + (uint32_t)((b_row + inp * 16) * ROW_B +
                                                 (s * 2 + b_cg) * 16));
#pragma unroll
            for (int im = 0; im < 4; im++)
#pragma unroll
                for (int in = 0; in < 4; in++)
                    mma_f16(acc[im][in], af[im], &bf[in >> 1][(in & 1) * 2]);
        }
    };

    fill(0, 0); CP_COMMIT();
    fill(1, 1); CP_COMMIT();

    for (int kb = 0; kb < NC; kb += 3) {
#pragma unroll
        for (int u = 0; u < 3; u++) {
            const int kc = kb + u;
            CP_WAIT1();
            __syncthreads();
            if (kc + 2 < NC) fill(kc + 2, (u + 2) % 3);
            CP_COMMIT();
            mma_stage(u);
        }
    }

    const int rq = lane >> 2;
    const int cq = (lane & 3) * 2;
#pragma unroll
    for (int im = 0; im < 4; im++) {
        const int row0 = bm + warp_m + im * 16 + rq;
#pragma unroll
        for (int in = 0; in < 4; in++) {
            const int col = bn + warp_n + in * 8 + cq;
            const float2 bv = *(const float2*)(bias + col);
            float v0 = acc[im][in][0] + bv.x;
            float v1 = acc[im][in][1] + bv.y;
            float v2 = acc[im][in][2] + bv.x;
            float v3 = acc[im][in][3] + bv.y;
            if (ACT == 1) {
                v0 = 0.5f * v0 * (1.0f + erff(v0 * 0.70710678118654752f));
                v1 = 0.5f * v1 * (1.0f + erff(v1 * 0.70710678118654752f));
                v2 = 0.5f * v2 * (1.0f + erff(v2 * 0.70710678118654752f));
                v3 = 0.5f * v3 * (1.0f + erff(v3 * 0.70710678118654752f));
            }
            if (OMODE == 1) {
                *(__half2*)(Ch + (size_t)row0 * N + col) =
                    __halves2half2(__float2half_rn(v0), __float2half_rn(v1));
                *(__half2*)(Ch + (size_t)(row0 + 8) * N + col) =
                    __halves2half2(__float2half_rn(v2), __float2half_rn(v3));
            } else {
                if (R) {
                    const float2 r0 = *(const float2*)(R + (size_t)row0 * N + col);
                    const float2 r1 = *(const float2*)(R + (size_t)(row0 + 8) * N + col);
                    v0 += r0.x; v1 += r0.y; v2 += r1.x; v3 += r1.y;
                }
                if (OMODE == 2) {
                    Cf[bchw_idx(row0,     col)]     = v0;
                    Cf[bchw_idx(row0,     col + 1)] = v1;
                    Cf[bchw_idx(row0 + 8, col)]     = v2;
                    Cf[bchw_idx(row0 + 8, col + 1)] = v3;
                } else {
                    *(float2*)(Cf + (size_t)row0 * N + col)       = make_float2(v0, v1);
                    *(float2*)(Cf + (size_t)(row0 + 8) * N + col) = make_float2(v2, v3);
                }
            }
        }
    }
}

// ---------------------------------------------------------------------------
// 4) Window attention: fp16 mma, online softmax 2 chunks, ONE head per CTA,
//    256 threads (8 warps) -> halved load phase + better tile balance, occ 2.
// ---------------------------------------------------------------------------
#define AQ_STR 40
#define AROWS  208
#define ATTN_SMEM (3 * AROWS * AQ_STR * 2)      // 49920 B

__global__ __launch_bounds__(256, 2)
void attn_h_kernel(const __half* __restrict__ QKV, __half* __restrict__ ATT)
{
    const int wi  = blockIdx.x / NH;
    const int hdi = blockIdx.x % NH;

    extern __shared__ __half shh[];
    __half* qs = shh;
    __half* ks = qs + AROWS * AQ_STR;
    __half* vs = ks + AROWS * AQ_STR;

    const int tid  = threadIdx.x;
    const int warp = tid >> 5;
    const int lane = tid & 31;
    const float scale = 0.1767766952966369f;   // 1/sqrt(32)

    const __half* base = QKV + (size_t)wi * NTOK * (3 * DIM) + hdi * HD;
    for (int idx = tid; idx < AROWS * 4; idx += 256) {
        const int row = idx >> 2, c = idx & 3;
        uint4 q = make_uint4(0, 0, 0, 0), k = q, v = q;
        if (row < NTOK) {
            const __half* src = base + (size_t)row * (3 * DIM) + c * 8;
            q = *(const uint4*)(src);
            k = *(const uint4*)(src + DIM);
            v = *(const uint4*)(src + 2 * DIM);
        }
        *(uint4*)(qs + row * AQ_STR + c * 8) = q;
        *(uint4*)(ks + row * AQ_STR + c * 8) = k;
        *(uint4*)(vs + row * AQ_STR + c * 8) = v;
    }
    __syncthreads();

    const uint32_t qb = smem_u32(qs);
    const uint32_t kb = smem_u32(ks);
    const uint32_t vb = smem_u32(vs);

    const int g  = lane >> 3;
    const int r8 = lane & 7;
    const int a_row_off = (g & 1) * 8 + r8;
    const int a_cg      = (g >> 1) * 16;
    const int b_row_off = (g >> 1) * 8 + r8;
    const int b_cg      = (g & 1) * 16;

    const int rq  = lane >> 2;
    const int cq2 = (lane & 3) * 2;

    for (int t = warp; t < 13; t += 8) {
        const int m0 = t * 16;

        uint32_t af[2][4];
#pragma unroll
        for (int s = 0; s < 2; s++)
            ldsm_x4(af[s], qb + (uint32_t)((m0 + a_row_off) * 80 + a_cg + s * 32));

        float m0r = -1e30f, m1r = -1e30f;
        float s0 = 0.f, s1 = 0.f;
        float o[4][4];
#pragma unroll
        for (int n = 0; n < 4; n++) { o[n][0] = o[n][1] = o[n][2] = o[n][3] = 0.f; }

#pragma unroll
        for (int ch = 0; ch < 2; ch++) {
            const int NT    = ch ? 12 : 14;
            const int base8 = ch ? 112 : 0;

            float c[14][4];
#pragma unroll
            for (int nt = 0; nt < 14; nt++) { c[nt][0] = c[nt][1] = c[nt][2] = c[nt][3] = 0.f; }
#pragma unroll
            for (int np = 0; np < 7; np++) {
                if (np >= NT / 2) break;
#pragma unroll
                for (int s = 0; s < 2; s++) {
                    uint32_t bf[4];
                    ldsm_x4(bf, kb + (uint32_t)((base8 + np * 16 + b_row_off) * 80 + b_cg + s * 32));
                    mma_f16(c[2 * np],     af[s], &bf[0]);
                    mma_f16(c[2 * np + 1], af[s], &bf[2]);
                }
            }

            float mx0 = -1e30f, mx1 = -1e30f;
#pragma unroll
            for (int nt = 0; nt < 14; nt++) {
                if (nt >= NT) break;
                const int col = base8 + nt * 8 + cq2;
                const bool ok0 = (ch == 0) || (col < NTOK);
                const bool ok1 = (ch == 0) || (col + 1 < NTOK);
                if (ok0) { mx0 = fmaxf(mx0, c[nt][0]); mx1 = fmaxf(mx1, c[nt][2]); }
                if (ok1) { mx0 = fmaxf(mx0, c[nt][1]); mx1 = fmaxf(mx1, c[nt][3]); }
            }
            mx0 = fmaxf(mx0, __shfl_xor_sync(0xffffffffu, mx0, 1));
            mx0 = fmaxf(mx0, __shfl_xor_sync(0xffffffffu, mx0, 2));
            mx1 = fmaxf(mx1, __shfl_xor_sync(0xffffffffu, mx1, 1));
            mx1 = fmaxf(mx1, __shfl_xor_sync(0xffffffffu, mx1, 2));

            const float nm0 = fmaxf(m0r, mx0);
            const float nm1 = fmaxf(m1r, mx1);
            const float r0 = __expf((m0r - nm0) * scale);
            const float r1 = __expf((m1r - nm1) * scale);
            m0r = nm0; m1r = nm1;

            uint32_t ph[14][2];
            float cs0 = 0.f, cs1 = 0.f;
#pragma unroll
            for (int nt = 0; nt < 14; nt++) {
                if (nt >= NT) break;
                const int col = base8 + nt * 8 + cq2;
                const bool ok0 = (ch == 0) || (col < NTOK);
                const bool ok1 = (ch == 0) || (col + 1 < NTOK);
                float p0 = ok0 ? __expf((c[nt][0] - nm0) * scale) : 0.f;
                float p1 = ok1 ? __expf((c[nt][1] - nm0) * scale) : 0.f;
                float p2 = ok0 ? __expf((c[nt][2] - nm1) * scale) : 0.f;
                float p3 = ok1 ? __expf((c[nt][3] - nm1) * scale) : 0.f;
                cs0 += p0 + p1;
                cs1 += p2 + p3;
                ph[nt][0] = pack_h2(p0, p1);
                ph[nt][1] = pack_h2(p2, p3);
            }
            cs0 += __shfl_xor_sync(0xffffffffu, cs0, 1);
            cs0 += __shfl_xor_sync(0xffffffffu, cs0, 2);
            cs1 += __shfl_xor_sync(0xffffffffu, cs1, 1);
            cs1 += __shfl_xor_sync(0xffffffffu, cs1, 2);
            s0 = s0 * r0 + cs0;
            s1 = s1 * r1 + cs1;

#pragma unroll
            for (int n = 0; n < 4; n++) {
                o[n][0] *= r0; o[n][1] *= r0;
                o[n][2] *= r1; o[n][3] *= r1;
            }

#pragma unroll
            for (int kt = 0; kt < 7; kt++) {
                if (kt >= NT / 2) break;
                uint32_t a[4] = { ph[2 * kt][0], ph[2 * kt][1],
                                  ph[2 * kt + 1][0], ph[2 * kt + 1][1] };
                uint32_t v0f[4], v1f[4];
                ldsm_x4_t(v0f, vb + (uint32_t)((base8 + kt * 16 + a_row_off) * 80 + a_cg));
                ldsm_x4_t(v1f, vb + (uint32_t)((base8 + kt * 16 + a_row_off) * 80 + a_cg + 32));
                mma_f16(o[0], a, &v0f[0]);
                mma_f16(o[1], a, &v0f[2]);
                mma_f16(o[2], a, &v1f[0]);
                mma_f16(o[3], a, &v1f[2]);
            }
        }

        const float inv0 = 1.0f / s0;
        const float inv1 = 1.0f / s1;
        const int rr0 = m0 + rq, rr1 = m0 + rq + 8;
#pragma unroll
        for (int n = 0; n < 4; n++) {
            const int col = hdi * HD + n * 8 + cq2;
            if (rr0 < NTOK)
                *(__half2*)(ATT + ((size_t)wi * NTOK + rr0) * DIM + col) =
                    __halves2half2(__float2half_rn(o[n][0] * inv0), __float2half_rn(o[n][1] * inv0));
            if (rr1 < NTOK)
                *(__half2*)(ATT + ((size_t)wi * NTOK + rr1) * DIM + col) =
                    __halves2half2(__float2half_rn(o[n][2] * inv1), __float2half_rn(o[n][3] * inv1));
        }
    }
}

// ---------------------------------------------------------------------------
// Launch
// ---------------------------------------------------------------------------
extern "C" void kernel_launch(void* const* d_in, const int* in_sizes, int n_in,
                              void* d_out, int out_size)
{
    const float* x      = (const float*)d_in[0];
    const float* conv_w = (const float*)d_in[1];
    const float* conv_b = (const float*)d_in[2];
    const float* ln1_g  = (const float*)d_in[3];
    const float* ln1_b  = (const float*)d_in[4];
    const float* qkv_w  = (const float*)d_in[5];
    const float* qkv_b  = (const float*)d_in[6];
    const float* proj_w = (const float*)d_in[7];
    const float* proj_b = (const float*)d_in[8];
    const float* ln2_g  = (const float*)d_in[9];
    const float* ln2_b  = (const float*)d_in[10];
    const float* fc1_w  = (const float*)d_in[11];
    const float* fc1_b  = (const float*)d_in[12];
    const float* fc2_w  = (const float*)d_in[13];
    const float* fc2_b  = (const float*)d_in[14];
    float* out = (float*)d_out;

    float *X0, *X1;
    __half *Y, *QKV, *ATT, *F, *Wh;
    cudaGetSymbolAddress((void**)&X0,  g_X0);
    cudaGetSymbolAddress((void**)&Y,   g_Y);
    cudaGetSymbolAddress((void**)&QKV, g_QKV);
    cudaGetSymbolAddress((void**)&ATT, g_ATT);
    cudaGetSymbolAddress((void**)&X1,  g_X1);
    cudaGetSymbolAddress((void**)&F,   g_F);
    cudaGetSymbolAddress((void**)&Wh,  g_Wh);

    cudaFuncSetAttribute(attn_h_kernel, cudaFuncAttributeMaxDynamicSharedMemorySize, ATTN_SMEM);
    cudaFuncSetAttribute(hgemm_kernel<1152, 384, 0, 1>, cudaFuncAttributeMaxDynamicSharedMemorySize, GEMM_SMEM);
    cudaFuncSetAttribute(hgemm_kernel<384, 384, 0, 0>,  cudaFuncAttributeMaxDynamicSharedMemorySize, GEMM_SMEM);
    cudaFuncSetAttribute(hgemm_kernel<1536, 384, 1, 1>, cudaFuncAttributeMaxDynamicSharedMemorySize, GEMM_SMEM);
    cudaFuncSetAttribute(hgemm_kernel<384, 1536, 0, 2>, cudaFuncAttributeMaxDynamicSharedMemorySize, GEMM_SMEM);

    // 0) fp16 weights
    cvtw_all_kernel<<<(1769472 + 255) / 256, 256>>>(qkv_w, proj_w, fc1_w, fc2_w, Wh);

    // 1) conv PE + residual -> X0
    conv_pe_kernel<<<dim3(DIM / 8, HH / 4, BATCH), dim3(8, 56)>>>(x, conv_w, conv_b, X0);

    // 2) LN1 -> Y (fp16)
    ln_kernel<<<TOK / 8, 256>>>(X0, ln1_g, ln1_b, Y);

    // 3) QKV GEMM
    hgemm_kernel<1152, 384, 0, 1><<<dim3(1152 / BN, TOK / BM), 256, GEMM_SMEM>>>(
        Y, Wh + WOFF_QKV, qkv_b, nullptr, nullptr, QKV);

    // 4) window attention (1 head/CTA, 256 threads, occ 2)
    attn_h_kernel<<<NWIN * NH, 256, ATTN_SMEM>>>(QKV, ATT);

    // 5) proj GEMM + residual(X0) -> X1
    hgemm_kernel<384, 384, 0, 0><<<dim3(384 / BN, TOK / BM), 256, GEMM_SMEM>>>(
        ATT, Wh + WOFF_PROJ, proj_b, X0, X1, nullptr);

    // 6) LN2 -> Y (fp16)
    ln_kernel<<<TOK / 8, 256>>>(X1, ln2_g, ln2_b, Y);

    // 7) FC1 GEMM + GELU -> F (fp16)
    hgemm_kernel<1536, 384, 1, 1><<<dim3(1536 / BN, TOK / BM), 256, GEMM_SMEM>>>(
        Y, Wh + WOFF_FC1, fc1_b, nullptr, nullptr, F);

    // 8) FC2 GEMM + residual(X1) -> out (BCHW scatter)
    hgemm_kernel<384, 1536, 0, 2><<<dim3(384 / BN, TOK / BM), 256, GEMM_SMEM>>>(
        F, Wh + WOFF_FC2, fc2_b, X1, out, nullptr);
}

// round 16
// speedup vs baseline: 1.0803x; 1.0063x over previous
#include <cuda_runtime.h>
#include <cuda_bf16.h>
#include <cuda_fp16.h>
#include <math.h>
#include <cstdint>

// ---------------------------------------------------------------------------
// Problem constants
// ---------------------------------------------------------------------------
#define DIM   384
#define NH    12
#define HD    32
#define WS    14
#define BATCH 16
#define HH    56
#define WW    56
#define NWIN  256
#define NTOK  196
#define TOK   50176          // NWIN*NTOK

// ---------------------------------------------------------------------------
// Scratch (residual stream X0/X1 now fp16)
// ---------------------------------------------------------------------------
__device__ __align__(16) __half g_X0 [(size_t)TOK * DIM];
__device__ __align__(16) __half g_Y  [(size_t)TOK * DIM];
__device__ __align__(16) __half g_QKV[(size_t)TOK * 3 * DIM];
__device__ __align__(16) __half g_ATT[(size_t)TOK * DIM];
__device__ __align__(16) __half g_X1 [(size_t)TOK * DIM];
__device__ __align__(16) __half g_F  [(size_t)TOK * 4 * DIM];
__device__ __align__(16) __half g_Wh [1769472];          // fp16 weights

#define N_QKV  (3 * DIM * DIM)
#define N_PROJ (DIM * DIM)
#define N_FC   (4 * DIM * DIM)
#define WOFF_QKV  0
#define WOFF_PROJ N_QKV
#define WOFF_FC1  (WOFF_PROJ + N_PROJ)
#define WOFF_FC2  (WOFF_FC1 + N_FC)

// ---------------------------------------------------------------------------
// helpers
// ---------------------------------------------------------------------------
__device__ __forceinline__ uint32_t smem_u32(const void* p) {
    uint32_t a;
    asm("{ .reg .u64 t; cvta.to.shared.u64 t, %1; cvt.u32.u64 %0, t; }" : "=r"(a) : "l"(p));
    return a;
}
__device__ __forceinline__ void cp16(uint32_t dst, const void* src) {
    asm volatile("cp.async.cg.shared.global [%0], [%1], 16;" :: "r"(dst), "l"(src));
}
#define CP_COMMIT() asm volatile("cp.async.commit_group;" ::: "memory")
#define CP_WAIT1()  asm volatile("cp.async.wait_group 1;" ::: "memory")

__device__ __forceinline__ void ldsm_x4(uint32_t* r, uint32_t a) {
    asm volatile("ldmatrix.sync.aligned.m8n8.x4.shared.b16 {%0,%1,%2,%3}, [%4];"
                 : "=r"(r[0]), "=r"(r[1]), "=r"(r[2]), "=r"(r[3]) : "r"(a));
}
__device__ __forceinline__ void ldsm_x4_t(uint32_t* r, uint32_t a) {
    asm volatile("ldmatrix.sync.aligned.m8n8.x4.trans.shared.b16 {%0,%1,%2,%3}, [%4];"
                 : "=r"(r[0]), "=r"(r[1]), "=r"(r[2]), "=r"(r[3]) : "r"(a));
}
__device__ __forceinline__ void mma_f16(float* d, const uint32_t* a, const uint32_t* b) {
    asm volatile(
        "mma.sync.aligned.m16n8k16.row.col.f32.f16.f16.f32 "
        "{%0,%1,%2,%3}, {%4,%5,%6,%7}, {%8,%9}, {%0,%1,%2,%3};"
        : "+f"(d[0]), "+f"(d[1]), "+f"(d[2]), "+f"(d[3])
        : "r"(a[0]), "r"(a[1]), "r"(a[2]), "r"(a[3]), "r"(b[0]), "r"(b[1]));
}
__device__ __forceinline__ uint32_t pack_h2(float x, float y) {
    __half2 h = __floats2half2_rn(x, y);
    return *reinterpret_cast<uint32_t*>(&h);
}
// token index m, channel c -> BCHW flat index
__device__ __forceinline__ int bchw_idx(int m, int c) {
    const int wi = m / NTOK;
    const int n  = m % NTOK;
    const int b  = wi >> 4;
    const int q  = wi & 15;
    const int h  = (q >> 2) * WS + n / WS;
    const int w  = (q & 3) * WS + n % WS;
    return ((b * DIM + c) * HH + h) * WW + w;
}

// ---------------------------------------------------------------------------
// 0) all four weight conversions in ONE launch
// ---------------------------------------------------------------------------
__global__ void cvtw_all_kernel(const float* __restrict__ qkv_w,
                                const float* __restrict__ proj_w,
                                const float* __restrict__ fc1_w,
                                const float* __restrict__ fc2_w,
                                __half* __restrict__ dst)
{
    int i = blockIdx.x * blockDim.x + threadIdx.x;
    if (i >= 1769472) return;
    float v;
    if (i < WOFF_PROJ)                v = qkv_w[i];
    else if (i < WOFF_FC1)            v = proj_w[i - WOFF_PROJ];
    else if (i < WOFF_FC2)            v = fc1_w[i - WOFF_FC1];
    else                              v = fc2_w[i - WOFF_FC2];
    dst[i] = __float2half_rn(v);
}

// ---------------------------------------------------------------------------
// 1) depthwise 3x3 conv PE + residual -> windowed (wi,n,c), fp16 out
// ---------------------------------------------------------------------------
__global__ void conv_pe_kernel(const float* __restrict__ x,
                               const float* __restrict__ cw,
                               const float* __restrict__ cb,
                               __half* __restrict__ X0)
{
    const int cg = blockIdx.x * 8;
    const int h0 = blockIdx.y * 4;
    const int b  = blockIdx.z;

    __shared__ float sm[8][6][58];

    const int tid = threadIdx.y * 8 + threadIdx.x;
    const int lc  = tid / 56;
    const int lw  = tid % 56;

    const float* xp = x + ((size_t)(b * DIM + cg + lc) * HH) * WW;
#pragma unroll
    for (int r = 0; r < 6; r++) {
        int hh = h0 - 1 + r;
        float v = (hh >= 0 && hh < HH) ? xp[hh * WW + lw] : 0.0f;
        sm[lc][r][lw + 1] = v;
        if (lw == 0)  sm[lc][r][0]  = 0.0f;
        if (lw == 55) sm[lc][r][57] = 0.0f;
    }
    __syncthreads();

    const int c = threadIdx.x;
    const int w = threadIdx.y;

    float wreg[9];
    const float* cwp = cw + (size_t)(cg + c) * 9;
#pragma unroll
    for (int i = 0; i < 9; i++) wreg[i] = cwp[i];
    const float cbv = cb[cg + c];

#pragma unroll
    for (int j = 0; j < 4; j++) {
        const int h = h0 + j;
        float pe = 0.0f;
#pragma unroll
        for (int kh = 0; kh < 3; kh++)
#pragma unroll
            for (int kw = 0; kw < 3; kw++)
                pe += wreg[kh * 3 + kw] * sm[c][j + kh][w + kw];

        const float val = sm[c][j + 1][w + 1] + pe + cbv;

        const int wi = (b * 4 + h / WS) * 4 + (w / WS);
        const int n  = (h % WS) * WS + (w % WS);
        X0[((size_t)wi * NTOK + n) * DIM + cg + c] = __float2half_rn(val);
    }
}

// ---------------------------------------------------------------------------
// 2) LayerNorm; fp16 in / fp16 out, half2-vectorized
// ---------------------------------------------------------------------------
__global__ void ln_kernel(const __half* __restrict__ X,
                          const float* __restrict__ gamma,
                          const float* __restrict__ beta,
                          __half* __restrict__ Y)
{
    const int warp = (blockIdx.x * blockDim.x + threadIdx.x) >> 5;
    const int lane = threadIdx.x & 31;
    if (warp >= TOK) return;

    const __half2* xp = (const __half2*)(X + (size_t)warp * DIM);
    float v[12];
    float s = 0.0f;
#pragma unroll
    for (int k = 0; k < 6; k++) {
        const float2 f = __half22float2(xp[lane + 32 * k]);
        v[2 * k]     = f.x;
        v[2 * k + 1] = f.y;
        s += f.x + f.y;
    }
#pragma unroll
    for (int o = 16; o; o >>= 1) s += __shfl_xor_sync(0xffffffffu, s, o);
    const float mean = s * (1.0f / DIM);

    float q = 0.0f;
#pragma unroll
    for (int k = 0; k < 12; k++) { float d = v[k] - mean; q += d * d; }
#pragma unroll
    for (int o = 16; o; o >>= 1) q += __shfl_xor_sync(0xffffffffu, q, o);
    const float inv = rsqrtf(q * (1.0f / DIM) + 1e-5f);

    __half2* yp = (__half2*)(Y + (size_t)warp * DIM);
#pragma unroll
    for (int k = 0; k < 6; k++) {
        const int c = 64 * k + 2 * lane;
        yp[lane + 32 * k] = __floats2half2_rn(
            (v[2 * k]     - mean) * inv * gamma[c]     + beta[c],
            (v[2 * k + 1] - mean) * inv * gamma[c + 1] + beta[c + 1]);
    }
}

// ---------------------------------------------------------------------------
// 3) FP16 mma.sync GEMM, compile-time shapes, K-loop unrolled by 3. [frozen]
//    CTA 128x128, BK=64, 8 warps (2m x 4n), warp 64x32, 3-stage, occ 2.
//    OMODE: 0 = fp16 out (+optional fp16 residual), 2 = BCHW fp32 scatter (+R)
// ---------------------------------------------------------------------------
#define BM 128
#define BN 128
#define BK 64
#define ROW_B 144
#define A_BYTES (128 * ROW_B)
#define STAGE_B (2 * A_BYTES)
#define NSTAGE  3
#define GEMM_SMEM (NSTAGE * STAGE_B)

template<int N, int K, int ACT, int OMODE>
__global__ __launch_bounds__(256, 2)
void hgemm_kernel(const __half* __restrict__ A,
                  const __half* __restrict__ W,
                  const float* __restrict__ bias,
                  const __half* __restrict__ Rh,
                  float* __restrict__ Cf,
                  __half* __restrict__ Ch)
{
    extern __shared__ char smc[];
    const uint32_t smem_base = smem_u32(smc);
    const int tid  = threadIdx.x;
    const int lane = tid & 31;
    const int wid  = tid >> 5;
    const int bm = blockIdx.y * BM;
    const int bn = blockIdx.x * BN;

    const int warp_m = (wid & 1) * 64;
    const int warp_n = (wid >> 1) * 32;

    float acc[4][4][4];
#pragma unroll
    for (int im = 0; im < 4; im++)
#pragma unroll
        for (int in = 0; in < 4; in++)
#pragma unroll
            for (int j = 0; j < 4; j++) acc[im][in][j] = 0.0f;

    const int g  = lane >> 3;
    const int r8 = lane & 7;
    const int a_row = warp_m + (g & 1) * 8 + r8;
    const int a_cg  = g >> 1;
    const int b_row = warp_n + (g >> 1) * 8 + r8;
    const int b_cg  = g & 1;

    constexpr int NC = K >> 6;
    static_assert(NC % 3 == 0, "NC must be divisible by NSTAGE");

    const int fr  = tid >> 1;
    const int fc0 = (tid & 1) * 4;
    auto fill = [&](int kc, int st) {
        const int k0 = kc << 6;
        const uint32_t sb = smem_base + (uint32_t)st * STAGE_B;
        const __half* Ag = A + (size_t)(bm + fr) * K + k0;
        const __half* Wg = W + (size_t)(bn + fr) * K + k0;
#pragma unroll
        for (int c = 0; c < 4; c++) {
            const int cc = fc0 + c;
            const uint32_t so = (uint32_t)(fr * ROW_B + cc * 16);
            cp16(sb + so, Ag + cc * 8);
            cp16(sb + A_BYTES + so, Wg + cc * 8);
        }
    };

    auto mma_stage = [&](int st) {
        const uint32_t ab = smem_base + (uint32_t)st * STAGE_B;
        const uint32_t bb = ab + A_BYTES;
#pragma unroll
        for (int s = 0; s < 4; s++) {
            uint32_t af[4][4], bf[2][4];
#pragma unroll
            for (int im = 0; im < 4; im++)
                ldsm_x4(af[im], ab + (uint32_t)((a_row + im * 16) * ROW_B +
                                                (s * 2 + a_cg) * 16));
#pragma unroll
            for (int inp = 0; inp < 2; inp++)
                ldsm_x4(bf[inp], bb + (uint32_t)((b_row + inp * 16) * ROW_B +
                                                 (s * 2 + b_cg) * 16));
#pragma unroll
            for (int im = 0; im < 4; im++)
#pragma unroll
                for (int in = 0; in < 4; in++)
                    mma_f16(acc[im][in], af[im], &bf[in >> 1][(in & 1) * 2]);
        }
    };

    fill(0, 0); CP_COMMIT();
    fill(1, 1); CP_COMMIT();

    for (int kb = 0; kb < NC; kb += 3) {
#pragma unroll
        for (int u = 0; u < 3; u++) {
            const int kc = kb + u;
            CP_WAIT1();
            __syncthreads();
            if (kc + 2 < NC) fill(kc + 2, (u + 2) % 3);
            CP_COMMIT();
            mma_stage(u);
        }
    }

    const int rq = lane >> 2;
    const int cq = (lane & 3) * 2;
#pragma unroll
    for (int im = 0; im < 4; im++) {
        const int row0 = bm + warp_m + im * 16 + rq;
#pragma unroll
        for (int in = 0; in < 4; in++) {
            const int col = bn + warp_n + in * 8 + cq;
            const float2 bv = *(const float2*)(bias + col);
            float v0 = acc[im][in][0] + bv.x;
            float v1 = acc[im][in][1] + bv.y;
            float v2 = acc[im][in][2] + bv.x;
            float v3 = acc[im][in][3] + bv.y;
            if (ACT == 1) {
                v0 = 0.5f * v0 * (1.0f + erff(v0 * 0.70710678118654752f));
                v1 = 0.5f * v1 * (1.0f + erff(v1 * 0.70710678118654752f));
                v2 = 0.5f * v2 * (1.0f + erff(v2 * 0.70710678118654752f));
                v3 = 0.5f * v3 * (1.0f + erff(v3 * 0.70710678118654752f));
            }
            if (Rh) {
                const float2 r0 = __half22float2(*(const __half2*)(Rh + (size_t)row0 * N + col));
                const float2 r1 = __half22float2(*(const __half2*)(Rh + (size_t)(row0 + 8) * N + col));
                v0 += r0.x; v1 += r0.y; v2 += r1.x; v3 += r1.y;
            }
            if (OMODE == 2) {
                Cf[bchw_idx(row0,     col)]     = v0;
                Cf[bchw_idx(row0,     col + 1)] = v1;
                Cf[bchw_idx(row0 + 8, col)]     = v2;
                Cf[bchw_idx(row0 + 8, col + 1)] = v3;
            } else {
                *(__half2*)(Ch + (size_t)row0 * N + col) =
                    __halves2half2(__float2half_rn(v0), __float2half_rn(v1));
                *(__half2*)(Ch + (size_t)(row0 + 8) * N + col) =
                    __halves2half2(__float2half_rn(v2), __float2half_rn(v3));
            }
        }
    }
}

// ---------------------------------------------------------------------------
// 4) Window attention (frozen best): fp16 mma, online softmax 2 chunks,
//    one head per CTA, 256 threads, occupancy 2.
// ---------------------------------------------------------------------------
#define AQ_STR 40
#define AROWS  208
#define ATTN_SMEM (3 * AROWS * AQ_STR * 2)      // 49920 B

__global__ __launch_bounds__(256, 2)
void attn_h_kernel(const __half* __restrict__ QKV, __half* __restrict__ ATT)
{
    const int wi  = blockIdx.x / NH;
    const int hdi = blockIdx.x % NH;

    extern __shared__ __half shh[];
    __half* qs = shh;
    __half* ks = qs + AROWS * AQ_STR;
    __half* vs = ks + AROWS * AQ_STR;

    const int tid  = threadIdx.x;
    const int warp = tid >> 5;
    const int lane = tid & 31;
    const float scale = 0.1767766952966369f;   // 1/sqrt(32)

    const __half* base = QKV + (size_t)wi * NTOK * (3 * DIM) + hdi * HD;
    for (int idx = tid; idx < AROWS * 4; idx += 256) {
        const int row = idx >> 2, c = idx & 3;
        uint4 q = make_uint4(0, 0, 0, 0), k = q, v = q;
        if (row < NTOK) {
            const __half* src = base + (size_t)row * (3 * DIM) + c * 8;
            q = *(const uint4*)(src);
            k = *(const uint4*)(src + DIM);
            v = *(const uint4*)(src + 2 * DIM);
        }
        *(uint4*)(qs + row * AQ_STR + c * 8) = q;
        *(uint4*)(ks + row * AQ_STR + c * 8) = k;
        *(uint4*)(vs + row * AQ_STR + c * 8) = v;
    }
    __syncthreads();

    const uint32_t qb = smem_u32(qs);
    const uint32_t kb = smem_u32(ks);
    const uint32_t vb = smem_u32(vs);

    const int g  = lane >> 3;
    const int r8 = lane & 7;
    const int a_row_off = (g & 1) * 8 + r8;
    const int a_cg      = (g >> 1) * 16;
    const int b_row_off = (g >> 1) * 8 + r8;
    const int b_cg      = (g & 1) * 16;

    const int rq  = lane >> 2;
    const int cq2 = (lane & 3) * 2;

    for (int t = warp; t < 13; t += 8) {
        const int m0 = t * 16;

        uint32_t af[2][4];
#pragma unroll
        for (int s = 0; s < 2; s++)
            ldsm_x4(af[s], qb + (uint32_t)((m0 + a_row_off) * 80 + a_cg + s * 32));

        float m0r = -1e30f, m1r = -1e30f;
        float s0 = 0.f, s1 = 0.f;
        float o[4][4];
#pragma unroll
        for (int n = 0; n < 4; n++) { o[n][0] = o[n][1] = o[n][2] = o[n][3] = 0.f; }

#pragma unroll
        for (int ch = 0; ch < 2; ch++) {
            const int NT    = ch ? 12 : 14;
            const int base8 = ch ? 112 : 0;

            float c[14][4];
#pragma unroll
            for (int nt = 0; nt < 14; nt++) { c[nt][0] = c[nt][1] = c[nt][2] = c[nt][3] = 0.f; }
#pragma unroll
            for (int np = 0; np < 7; np++) {
                if (np >= NT / 2) break;
#pragma unroll
                for (int s = 0; s < 2; s++) {
                    uint32_t bf[4];
                    ldsm_x4(bf, kb + (uint32_t)((base8 + np * 16 + b_row_off) * 80 + b_cg + s * 32));
                    mma_f16(c[2 * np],     af[s], &bf[0]);
                    mma_f16(c[2 * np + 1], af[s], &bf[2]);
                }
            }

            float mx0 = -1e30f, mx1 = -1e30f;
#pragma unroll
            for (int nt = 0; nt < 14; nt++) {
                if (nt >= NT) break;
                const int col = base8 + nt * 8 + cq2;
                const bool ok0 = (ch == 0) || (col < NTOK);
                const bool ok1 = (ch == 0) || (col + 1 < NTOK);
                if (ok0) { mx0 = fmaxf(mx0, c[nt][0]); mx1 = fmaxf(mx1, c[nt][2]); }
                if (ok1) { mx0 = fmaxf(mx0, c[nt][1]); mx1 = fmaxf(mx1, c[nt][3]); }
            }
            mx0 = fmaxf(mx0, __shfl_xor_sync(0xffffffffu, mx0, 1));
            mx0 = fmaxf(mx0, __shfl_xor_sync(0xffffffffu, mx0, 2));
            mx1 = fmaxf(mx1, __shfl_xor_sync(0xffffffffu, mx1, 1));
            mx1 = fmaxf(mx1, __shfl_xor_sync(0xffffffffu, mx1, 2));

            const float nm0 = fmaxf(m0r, mx0);
            const float nm1 = fmaxf(m1r, mx1);
            const float r0 = __expf((m0r - nm0) * scale);
            const float r1 = __expf((m1r - nm1) * scale);
            m0r = nm0; m1r = nm1;

            uint32_t ph[14][2];
            float cs0 = 0.f, cs1 = 0.f;
#pragma unroll
            for (int nt = 0; nt < 14; nt++) {
                if (nt >= NT) break;
                const int col = base8 + nt * 8 + cq2;
                const bool ok0 = (ch == 0) || (col < NTOK);
                const bool ok1 = (ch == 0) || (col + 1 < NTOK);
                float p0 = ok0 ? __expf((c[nt][0] - nm0) * scale) : 0.f;
                float p1 = ok1 ? __expf((c[nt][1] - nm0) * scale) : 0.f;
                float p2 = ok0 ? __expf((c[nt][2] - nm1) * scale) : 0.f;
                float p3 = ok1 ? __expf((c[nt][3] - nm1) * scale) : 0.f;
                cs0 += p0 + p1;
                cs1 += p2 + p3;
                ph[nt][0] = pack_h2(p0, p1);
                ph[nt][1] = pack_h2(p2, p3);
            }
            cs0 += __shfl_xor_sync(0xffffffffu, cs0, 1);
            cs0 += __shfl_xor_sync(0xffffffffu, cs0, 2);
            cs1 += __shfl_xor_sync(0xffffffffu, cs1, 1);
            cs1 += __shfl_xor_sync(0xffffffffu, cs1, 2);
            s0 = s0 * r0 + cs0;
            s1 = s1 * r1 + cs1;

#pragma unroll
            for (int n = 0; n < 4; n++) {
                o[n][0] *= r0; o[n][1] *= r0;
                o[n][2] *= r1; o[n][3] *= r1;
            }

#pragma unroll
            for (int kt = 0; kt < 7; kt++) {
                if (kt >= NT / 2) break;
                uint32_t a[4] = { ph[2 * kt][0], ph[2 * kt][1],
                                  ph[2 * kt + 1][0], ph[2 * kt + 1][1] };
                uint32_t v0f[4], v1f[4];
                ldsm_x4_t(v0f, vb + (uint32_t)((base8 + kt * 16 + a_row_off) * 80 + a_cg));
                ldsm_x4_t(v1f, vb + (uint32_t)((base8 + kt * 16 + a_row_off) * 80 + a_cg + 32));
                mma_f16(o[0], a, &v0f[0]);
                mma_f16(o[1], a, &v0f[2]);
                mma_f16(o[2], a, &v1f[0]);
                mma_f16(o[3], a, &v1f[2]);
            }
        }

        const float inv0 = 1.0f / s0;
        const float inv1 = 1.0f / s1;
        const int rr0 = m0 + rq, rr1 = m0 + rq + 8;
#pragma unroll
        for (int n = 0; n < 4; n++) {
            const int col = hdi * HD + n * 8 + cq2;
            if (rr0 < NTOK)
                *(__half2*)(ATT + ((size_t)wi * NTOK + rr0) * DIM + col) =
                    __halves2half2(__float2half_rn(o[n][0] * inv0), __float2half_rn(o[n][1] * inv0));
            if (rr1 < NTOK)
                *(__half2*)(ATT + ((size_t)wi * NTOK + rr1) * DIM + col) =
                    __halves2half2(__float2half_rn(o[n][2] * inv1), __float2half_rn(o[n][3] * inv1));
        }
    }
}

// ---------------------------------------------------------------------------
// Launch
// ---------------------------------------------------------------------------
extern "C" void kernel_launch(void* const* d_in, const int* in_sizes, int n_in,
                              void* d_out, int out_size)
{
    const float* x      = (const float*)d_in[0];
    const float* conv_w = (const float*)d_in[1];
    const float* conv_b = (const float*)d_in[2];
    const float* ln1_g  = (const float*)d_in[3];
    const float* ln1_b  = (const float*)d_in[4];
    const float* qkv_w  = (const float*)d_in[5];
    const float* qkv_b  = (const float*)d_in[6];
    const float* proj_w = (const float*)d_in[7];
    const float* proj_b = (const float*)d_in[8];
    const float* ln2_g  = (const float*)d_in[9];
    const float* ln2_b  = (const float*)d_in[10];
    const float* fc1_w  = (const float*)d_in[11];
    const float* fc1_b  = (const float*)d_in[12];
    const float* fc2_w  = (const float*)d_in[13];
    const float* fc2_b  = (const float*)d_in[14];
    float* out = (float*)d_out;

    __half *X0, *X1, *Y, *QKV, *ATT, *F, *Wh;
    cudaGetSymbolAddress((void**)&X0,  g_X0);
    cudaGetSymbolAddress((void**)&Y,   g_Y);
    cudaGetSymbolAddress((void**)&QKV, g_QKV);
    cudaGetSymbolAddress((void**)&ATT, g_ATT);
    cudaGetSymbolAddress((void**)&X1,  g_X1);
    cudaGetSymbolAddress((void**)&F,   g_F);
    cudaGetSymbolAddress((void**)&Wh,  g_Wh);

    cudaFuncSetAttribute(attn_h_kernel, cudaFuncAttributeMaxDynamicSharedMemorySize, ATTN_SMEM);
    cudaFuncSetAttribute(hgemm_kernel<1152, 384, 0, 0>, cudaFuncAttributeMaxDynamicSharedMemorySize, GEMM_SMEM);
    cudaFuncSetAttribute(hgemm_kernel<384, 384, 0, 0>,  cudaFuncAttributeMaxDynamicSharedMemorySize, GEMM_SMEM);
    cudaFuncSetAttribute(hgemm_kernel<1536, 384, 1, 0>, cudaFuncAttributeMaxDynamicSharedMemorySize, GEMM_SMEM);
    cudaFuncSetAttribute(hgemm_kernel<384, 1536, 0, 2>, cudaFuncAttributeMaxDynamicSharedMemorySize, GEMM_SMEM);

    // 0) fp16 weights
    cvtw_all_kernel<<<(1769472 + 255) / 256, 256>>>(qkv_w, proj_w, fc1_w, fc2_w, Wh);

    // 1) conv PE + residual -> X0 (fp16)
    conv_pe_kernel<<<dim3(DIM / 8, HH / 4, BATCH), dim3(8, 56)>>>(x, conv_w, conv_b, X0);

    // 2) LN1 -> Y (fp16 in / fp16 out)
    ln_kernel<<<TOK / 8, 256>>>(X0, ln1_g, ln1_b, Y);

    // 3) QKV GEMM
    hgemm_kernel<1152, 384, 0, 0><<<dim3(1152 / BN, TOK / BM), 256, GEMM_SMEM>>>(
        Y, Wh + WOFF_QKV, qkv_b, nullptr, nullptr, QKV);

    // 4) window attention
    attn_h_kernel<<<NWIN * NH, 256, ATTN_SMEM>>>(QKV, ATT);

    // 5) proj GEMM + residual(X0, fp16) -> X1 (fp16)
    hgemm_kernel<384, 384, 0, 0><<<dim3(384 / BN, TOK / BM), 256, GEMM_SMEM>>>(
        ATT, Wh + WOFF_PROJ, proj_b, X0, nullptr, X1);

    // 6) LN2 -> Y (fp16)
    ln_kernel<<<TOK / 8, 256>>>(X1, ln2_g, ln2_b, Y);

    // 7) FC1 GEMM + GELU -> F (fp16)
    hgemm_kernel<1536, 384, 1, 0><<<dim3(1536 / BN, TOK / BM), 256, GEMM_SMEM>>>(
        Y, Wh + WOFF_FC1, fc1_b, nullptr, nullptr, F);

    // 8) FC2 GEMM + residual(X1, fp16) -> out (BCHW scatter, fp32)
    hgemm_kernel<384, 1536, 0, 2><<<dim3(384 / BN, TOK / BM), 256, GEMM_SMEM>>>(
        F, Wh + WOFF_FC2, fc2_b, X1, out, nullptr);
}

// round 17
// speedup vs baseline: 1.0899x; 1.0089x over previous
#include <cuda_runtime.h>
#include <cuda_bf16.h>
#include <cuda_fp16.h>
#include <math.h>
#include <cstdint>

// ---------------------------------------------------------------------------
// Problem constants
// ---------------------------------------------------------------------------
#define DIM   384
#define NH    12
#define HD    32
#define WS    14
#define BATCH 16
#define HH    56
#define WW    56
#define NWIN  256
#define NTOK  196
#define TOK   50176          // NWIN*NTOK

// ---------------------------------------------------------------------------
// Scratch (residual stream fp16)
// ---------------------------------------------------------------------------
__device__ __align__(16) __half g_X0 [(size_t)TOK * DIM];
__device__ __align__(16) __half g_Y  [(size_t)TOK * DIM];
__device__ __align__(16) __half g_QKV[(size_t)TOK * 3 * DIM];
__device__ __align__(16) __half g_ATT[(size_t)TOK * DIM];
__device__ __align__(16) __half g_X1 [(size_t)TOK * DIM];
__device__ __align__(16) __half g_F  [(size_t)TOK * 4 * DIM];
__device__ __align__(16) __half g_Wh [1769472];          // fp16 weights

#define N_QKV  (3 * DIM * DIM)
#define N_PROJ (DIM * DIM)
#define N_FC   (4 * DIM * DIM)
#define WOFF_QKV  0
#define WOFF_PROJ N_QKV
#define WOFF_FC1  (WOFF_PROJ + N_PROJ)
#define WOFF_FC2  (WOFF_FC1 + N_FC)

// ---------------------------------------------------------------------------
// helpers
// ---------------------------------------------------------------------------
__device__ __forceinline__ uint32_t smem_u32(const void* p) {
    uint32_t a;
    asm("{ .reg .u64 t; cvta.to.shared.u64 t, %1; cvt.u32.u64 %0, t; }" : "=r"(a) : "l"(p));
    return a;
}
__device__ __forceinline__ void cp16(uint32_t dst, const void* src) {
    asm volatile("cp.async.cg.shared.global [%0], [%1], 16;" :: "r"(dst), "l"(src));
}
#define CP_COMMIT() asm volatile("cp.async.commit_group;" ::: "memory")
#define CP_WAIT1()  asm volatile("cp.async.wait_group 1;" ::: "memory")

__device__ __forceinline__ void ldsm_x4(uint32_t* r, uint32_t a) {
    asm volatile("ldmatrix.sync.aligned.m8n8.x4.shared.b16 {%0,%1,%2,%3}, [%4];"
                 : "=r"(r[0]), "=r"(r[1]), "=r"(r[2]), "=r"(r[3]) : "r"(a));
}
__device__ __forceinline__ void ldsm_x4_t(uint32_t* r, uint32_t a) {
    asm volatile("ldmatrix.sync.aligned.m8n8.x4.trans.shared.b16 {%0,%1,%2,%3}, [%4];"
                 : "=r"(r[0]), "=r"(r[1]), "=r"(r[2]), "=r"(r[3]) : "r"(a));
}
__device__ __forceinline__ void mma_f16(float* d, const uint32_t* a, const uint32_t* b) {
    asm volatile(
        "mma.sync.aligned.m16n8k16.row.col.f32.f16.f16.f32 "
        "{%0,%1,%2,%3}, {%4,%5,%6,%7}, {%8,%9}, {%0,%1,%2,%3};"
        : "+f"(d[0]), "+f"(d[1]), "+f"(d[2]), "+f"(d[3])
        : "r"(a[0]), "r"(a[1]), "r"(a[2]), "r"(a[3]), "r"(b[0]), "r"(b[1]));
}
__device__ __forceinline__ uint32_t pack_h2(float x, float y) {
    __half2 h = __floats2half2_rn(x, y);
    return *reinterpret_cast<uint32_t*>(&h);
}
// token index m, channel c -> BCHW flat index
__device__ __forceinline__ int bchw_idx(int m, int c) {
    const int wi = m / NTOK;
    const int n  = m % NTOK;
    const int b  = wi >> 4;
    const int q  = wi & 15;
    const int h  = (q >> 2) * WS + n / WS;
    const int w  = (q & 3) * WS + n % WS;
    return ((b * DIM + c) * HH + h) * WW + w;
}

// ---------------------------------------------------------------------------
// 0) all four weight conversions in ONE launch
// ---------------------------------------------------------------------------
__global__ void cvtw_all_kernel(const float* __restrict__ qkv_w,
                                const float* __restrict__ proj_w,
                                const float* __restrict__ fc1_w,
                                const float* __restrict__ fc2_w,
                                __half* __restrict__ dst)
{
    int i = blockIdx.x * blockDim.x + threadIdx.x;
    if (i >= 1769472) return;
    float v;
    if (i < WOFF_PROJ)                v = qkv_w[i];
    else if (i < WOFF_FC1)            v = proj_w[i - WOFF_PROJ];
    else if (i < WOFF_FC2)            v = fc1_w[i - WOFF_FC1];
    else                              v = fc2_w[i - WOFF_FC2];
    dst[i] = __float2half_rn(v);
}

// ---------------------------------------------------------------------------
// 1) depthwise 3x3 conv PE + residual -> windowed (wi,n,c), fp16 out
//    8 output rows per CTA (10 input rows): x re-read 1.25x
//    grid (DIM/8, HH/8, BATCH), block (8, 56)
// ---------------------------------------------------------------------------
__global__ void conv_pe_kernel(const float* __restrict__ x,
                               const float* __restrict__ cw,
                               const float* __restrict__ cb,
                               __half* __restrict__ X0)
{
    const int cg = blockIdx.x * 8;
    const int h0 = blockIdx.y * 8;
    const int b  = blockIdx.z;

    __shared__ float sm[8][10][58];

    const int tid = threadIdx.y * 8 + threadIdx.x;
    const int lc  = tid / 56;
    const int lw  = tid % 56;

    const float* xp = x + ((size_t)(b * DIM + cg + lc) * HH) * WW;
#pragma unroll
    for (int r = 0; r < 10; r++) {
        int hh = h0 - 1 + r;
        float v = (hh >= 0 && hh < HH) ? xp[hh * WW + lw] : 0.0f;
        sm[lc][r][lw + 1] = v;
        if (lw == 0)  sm[lc][r][0]  = 0.0f;
        if (lw == 55) sm[lc][r][57] = 0.0f;
    }
    __syncthreads();

    const int c = threadIdx.x;
    const int w = threadIdx.y;

    float wreg[9];
    const float* cwp = cw + (size_t)(cg + c) * 9;
#pragma unroll
    for (int i = 0; i < 9; i++) wreg[i] = cwp[i];
    const float cbv = cb[cg + c];

#pragma unroll
    for (int j = 0; j < 8; j++) {
        const int h = h0 + j;
        float pe = 0.0f;
#pragma unroll
        for (int kh = 0; kh < 3; kh++)
#pragma unroll
            for (int kw = 0; kw < 3; kw++)
                pe += wreg[kh * 3 + kw] * sm[c][j + kh][w + kw];

        const float val = sm[c][j + 1][w + 1] + pe + cbv;

        const int wi = (b * 4 + h / WS) * 4 + (w / WS);
        const int n  = (h % WS) * WS + (w % WS);
        X0[((size_t)wi * NTOK + n) * DIM + cg + c] = __float2half_rn(val);
    }
}

// ---------------------------------------------------------------------------
// 2) LayerNorm; fp16 in / fp16 out, half2-vectorized, 512-thread blocks
// ---------------------------------------------------------------------------
__global__ void ln_kernel(const __half* __restrict__ X,
                          const float* __restrict__ gamma,
                          const float* __restrict__ beta,
                          __half* __restrict__ Y)
{
    const int warp = (blockIdx.x * blockDim.x + threadIdx.x) >> 5;
    const int lane = threadIdx.x & 31;
    if (warp >= TOK) return;

    const __half2* xp = (const __half2*)(X + (size_t)warp * DIM);
    float v[12];
    float s = 0.0f;
#pragma unroll
    for (int k = 0; k < 6; k++) {
        const float2 f = __half22float2(xp[lane + 32 * k]);
        v[2 * k]     = f.x;
        v[2 * k + 1] = f.y;
        s += f.x + f.y;
    }
#pragma unroll
    for (int o = 16; o; o >>= 1) s += __shfl_xor_sync(0xffffffffu, s, o);
    const float mean = s * (1.0f / DIM);

    float q = 0.0f;
#pragma unroll
    for (int k = 0; k < 12; k++) { float d = v[k] - mean; q += d * d; }
#pragma unroll
    for (int o = 16; o; o >>= 1) q += __shfl_xor_sync(0xffffffffu, q, o);
    const float inv = rsqrtf(q * (1.0f / DIM) + 1e-5f);

    __half2* yp = (__half2*)(Y + (size_t)warp * DIM);
#pragma unroll
    for (int k = 0; k < 6; k++) {
        const int c = 64 * k + 2 * lane;
        yp[lane + 32 * k] = __floats2half2_rn(
            (v[2 * k]     - mean) * inv * gamma[c]     + beta[c],
            (v[2 * k + 1] - mean) * inv * gamma[c + 1] + beta[c + 1]);
    }
}

// ---------------------------------------------------------------------------
// 3) FP16 mma.sync GEMM, compile-time shapes, K-loop unrolled by 3. [frozen]
//    CTA 128x128, BK=64, 8 warps (2m x 4n), warp 64x32, 3-stage, occ 2.
//    OMODE: 0 = fp16 out (+optional fp16 residual), 2 = BCHW fp32 scatter (+R)
// ---------------------------------------------------------------------------
#define BM 128
#define BN 128
#define BK 64
#define ROW_B 144
#define A_BYTES (128 * ROW_B)
#define STAGE_B (2 * A_BYTES)
#define NSTAGE  3
#define GEMM_SMEM (NSTAGE * STAGE_B)

template<int N, int K, int ACT, int OMODE>
__global__ __launch_bounds__(256, 2)
void hgemm_kernel(const __half* __restrict__ A,
                  const __half* __restrict__ W,
                  const float* __restrict__ bias,
                  const __half* __restrict__ Rh,
                  float* __restrict__ Cf,
                  __half* __restrict__ Ch)
{
    extern __shared__ char smc[];
    const uint32_t smem_base = smem_u32(smc);
    const int tid  = threadIdx.x;
    const int lane = tid & 31;
    const int wid  = tid >> 5;
    const int bm = blockIdx.y * BM;
    const int bn = blockIdx.x * BN;

    const int warp_m = (wid & 1) * 64;
    const int warp_n = (wid >> 1) * 32;

    float acc[4][4][4];
#pragma unroll
    for (int im = 0; im < 4; im++)
#pragma unroll
        for (int in = 0; in < 4; in++)
#pragma unroll
            for (int j = 0; j < 4; j++) acc[im][in][j] = 0.0f;

    const int g  = lane >> 3;
    const int r8 = lane & 7;
    const int a_row = warp_m + (g & 1) * 8 + r8;
    const int a_cg  = g >> 1;
    const int b_row = warp_n + (g >> 1) * 8 + r8;
    const int b_cg  = g & 1;

    constexpr int NC = K >> 6;
    static_assert(NC % 3 == 0, "NC must be divisible by NSTAGE");

    const int fr  = tid >> 1;
    const int fc0 = (tid & 1) * 4;
    auto fill = [&](int kc, int st) {
        const int k0 = kc << 6;
        const uint32_t sb = smem_base + (uint32_t)st * STAGE_B;
        const __half* Ag = A + (size_t)(bm + fr) * K + k0;
        const __half* Wg = W + (size_t)(bn + fr) * K + k0;
#pragma unroll
        for (int c = 0; c < 4; c++) {
            const int cc = fc0 + c;
            const uint32_t so = (uint32_t)(fr * ROW_B + cc * 16);
            cp16(sb + so, Ag + cc * 8);
            cp16(sb + A_BYTES + so, Wg + cc * 8);
        }
    };

    auto mma_stage = [&](int st) {
        const uint32_t ab = smem_base + (uint32_t)st * STAGE_B;
        const uint32_t bb = ab + A_BYTES;
#pragma unroll
        for (int s = 0; s < 4; s++) {
            uint32_t af[4][4], bf[2][4];
#pragma unroll
            for (int im = 0; im < 4; im++)
                ldsm_x4(af[im], ab + (uint32_t)((a_row + im * 16) * ROW_B +
                                                (s * 2 + a_cg) * 16));
#pragma unroll
            for (int inp = 0; inp < 2; inp++)
                ldsm_x4(bf[inp], bb + (uint32_t)((b_row + inp * 16) * ROW_B +
                                                 (s * 2 + b_cg) * 16));
#pragma unroll
            for (int im = 0; im < 4; im++)
#pragma unroll
                for (int in = 0; in < 4; in++)
                    mma_f16(acc[im][in], af[im], &bf[in >> 1][(in & 1) * 2]);
        }
    };

    fill(0, 0); CP_COMMIT();
    fill(1, 1); CP_COMMIT();

    for (int kb = 0; kb < NC; kb += 3) {
#pragma unroll
        for (int u = 0; u < 3; u++) {
            const int kc = kb + u;
            CP_WAIT1();
            __syncthreads();
            if (kc + 2 < NC) fill(kc + 2, (u + 2) % 3);
            CP_COMMIT();
            mma_stage(u);
        }
    }

    const int rq = lane >> 2;
    const int cq = (lane & 3) * 2;
#pragma unroll
    for (int im = 0; im < 4; im++) {
        const int row0 = bm + warp_m + im * 16 + rq;
#pragma unroll
        for (int in = 0; in < 4; in++) {
            const int col = bn + warp_n + in * 8 + cq;
            const float2 bv = *(const float2*)(bias + col);
            float v0 = acc[im][in][0] + bv.x;
            float v1 = acc[im][in][1] + bv.y;
            float v2 = acc[im][in][2] + bv.x;
            float v3 = acc[im][in][3] + bv.y;
            if (ACT == 1) {
                v0 = 0.5f * v0 * (1.0f + erff(v0 * 0.70710678118654752f));
                v1 = 0.5f * v1 * (1.0f + erff(v1 * 0.70710678118654752f));
                v2 = 0.5f * v2 * (1.0f + erff(v2 * 0.70710678118654752f));
                v3 = 0.5f * v3 * (1.0f + erff(v3 * 0.70710678118654752f));
            }
            if (Rh) {
                const float2 r0 = __half22float2(*(const __half2*)(Rh + (size_t)row0 * N + col));
                const float2 r1 = __half22float2(*(const __half2*)(Rh + (size_t)(row0 + 8) * N + col));
                v0 += r0.x; v1 += r0.y; v2 += r1.x; v3 += r1.y;
            }
            if (OMODE == 2) {
                Cf[bchw_idx(row0,     col)]     = v0;
                Cf[bchw_idx(row0,     col + 1)] = v1;
                Cf[bchw_idx(row0 + 8, col)]     = v2;
                Cf[bchw_idx(row0 + 8, col + 1)] = v3;
            } else {
                *(__half2*)(Ch + (size_t)row0 * N + col) =
                    __halves2half2(__float2half_rn(v0), __float2half_rn(v1));
                *(__half2*)(Ch + (size_t)(row0 + 8) * N + col) =
                    __halves2half2(__float2half_rn(v2), __float2half_rn(v3));
            }
        }
    }
}

// ---------------------------------------------------------------------------
// 4) Window attention (frozen best): fp16 mma, online softmax 2 chunks,
//    one head per CTA, 256 threads, occupancy 2.
// ---------------------------------------------------------------------------
#define AQ_STR 40
#define AROWS  208
#define ATTN_SMEM (3 * AROWS * AQ_STR * 2)      // 49920 B

__global__ __launch_bounds__(256, 2)
void attn_h_kernel(const __half* __restrict__ QKV, __half* __restrict__ ATT)
{
    const int wi  = blockIdx.x / NH;
    const int hdi = blockIdx.x % NH;

    extern __shared__ __half shh[];
    __half* qs = shh;
    __half* ks = qs + AROWS * AQ_STR;
    __half* vs = ks + AROWS * AQ_STR;

    const int tid  = threadIdx.x;
    const int warp = tid >> 5;
    const int lane = tid & 31;
    const float scale = 0.1767766952966369f;   // 1/sqrt(32)

    const __half* base = QKV + (size_t)wi * NTOK * (3 * DIM) + hdi * HD;
    for (int idx = tid; idx < AROWS * 4; idx += 256) {
        const int row = idx >> 2, c = idx & 3;
        uint4 q = make_uint4(0, 0, 0, 0), k = q, v = q;
        if (row < NTOK) {
            const __half* src = base + (size_t)row * (3 * DIM) + c * 8;
            q = *(const uint4*)(src);
            k = *(const uint4*)(src + DIM);
            v = *(const uint4*)(src + 2 * DIM);
        }
        *(uint4*)(qs + row * AQ_STR + c * 8) = q;
        *(uint4*)(ks + row * AQ_STR + c * 8) = k;
        *(uint4*)(vs + row * AQ_STR + c * 8) = v;
    }
    __syncthreads();

    const uint32_t qb = smem_u32(qs);
    const uint32_t kb = smem_u32(ks);
    const uint32_t vb = smem_u32(vs);

    const int g  = lane >> 3;
    const int r8 = lane & 7;
    const int a_row_off = (g & 1) * 8 + r8;
    const int a_cg      = (g >> 1) * 16;
    const int b_row_off = (g >> 1) * 8 + r8;
    const int b_cg      = (g & 1) * 16;

    const int rq  = lane >> 2;
    const int cq2 = (lane & 3) * 2;

    for (int t = warp; t < 13; t += 8) {
        const int m0 = t * 16;

        uint32_t af[2][4];
#pragma unroll
        for (int s = 0; s < 2; s++)
            ldsm_x4(af[s], qb + (uint32_t)((m0 + a_row_off) * 80 + a_cg + s * 32));

        float m0r = -1e30f, m1r = -1e30f;
        float s0 = 0.f, s1 = 0.f;
        float o[4][4];
#pragma unroll
        for (int n = 0; n < 4; n++) { o[n][0] = o[n][1] = o[n][2] = o[n][3] = 0.f; }

#pragma unroll
        for (int ch = 0; ch < 2; ch++) {
            const int NT    = ch ? 12 : 14;
            const int base8 = ch ? 112 : 0;

            float c[14][4];
#pragma unroll
            for (int nt = 0; nt < 14; nt++) { c[nt][0] = c[nt][1] = c[nt][2] = c[nt][3] = 0.f; }
#pragma unroll
            for (int np = 0; np < 7; np++) {
                if (np >= NT / 2) break;
#pragma unroll
                for (int s = 0; s < 2; s++) {
                    uint32_t bf[4];
                    ldsm_x4(bf, kb + (uint32_t)((base8 + np * 16 + b_row_off) * 80 + b_cg + s * 32));
                    mma_f16(c[2 * np],     af[s], &bf[0]);
                    mma_f16(c[2 * np + 1], af[s], &bf[2]);
                }
            }

            float mx0 = -1e30f, mx1 = -1e30f;
#pragma unroll
            for (int nt = 0; nt < 14; nt++) {
                if (nt >= NT) break;
                const int col = base8 + nt * 8 + cq2;
                const bool ok0 = (ch == 0) || (col < NTOK);
                const bool ok1 = (ch == 0) || (col + 1 < NTOK);
                if (ok0) { mx0 = fmaxf(mx0, c[nt][0]); mx1 = fmaxf(mx1, c[nt][2]); }
                if (ok1) { mx0 = fmaxf(mx0, c[nt][1]); mx1 = fmaxf(mx1, c[nt][3]); }
            }
            mx0 = fmaxf(mx0, __shfl_xor_sync(0xffffffffu, mx0, 1));
            mx0 = fmaxf(mx0, __shfl_xor_sync(0xffffffffu, mx0, 2));
            mx1 = fmaxf(mx1, __shfl_xor_sync(0xffffffffu, mx1, 1));
            mx1 = fmaxf(mx1, __shfl_xor_sync(0xffffffffu, mx1, 2));

            const float nm0 = fmaxf(m0r, mx0);
            const float nm1 = fmaxf(m1r, mx1);
            const float r0 = __expf((m0r - nm0) * scale);
            const float r1 = __expf((m1r - nm1) * scale);
            m0r = nm0; m1r = nm1;

            uint32_t ph[14][2];
            float cs0 = 0.f, cs1 = 0.f;
#pragma unroll
            for (int nt = 0; nt < 14; nt++) {
                if (nt >= NT) break;
                const int col = base8 + nt * 8 + cq2;
                const bool ok0 = (ch == 0) || (col < NTOK);
                const bool ok1 = (ch == 0) || (col + 1 < NTOK);
                float p0 = ok0 ? __expf((c[nt][0] - nm0) * scale) : 0.f;
                float p1 = ok1 ? __expf((c[nt][1] - nm0) * scale) : 0.f;
                float p2 = ok0 ? __expf((c[nt][2] - nm1) * scale) : 0.f;
                float p3 = ok1 ? __expf((c[nt][3] - nm1) * scale) : 0.f;
                cs0 += p0 + p1;
                cs1 += p2 + p3;
                ph[nt][0] = pack_h2(p0, p1);
                ph[nt][1] = pack_h2(p2, p3);
            }
            cs0 += __shfl_xor_sync(0xffffffffu, cs0, 1);
            cs0 += __shfl_xor_sync(0xffffffffu, cs0, 2);
            cs1 += __shfl_xor_sync(0xffffffffu, cs1, 1);
            cs1 += __shfl_xor_sync(0xffffffffu, cs1, 2);
            s0 = s0 * r0 + cs0;
            s1 = s1 * r1 + cs1;

#pragma unroll
            for (int n = 0; n < 4; n++) {
                o[n][0] *= r0; o[n][1] *= r0;
                o[n][2] *= r1; o[n][3] *= r1;
            }

#pragma unroll
            for (int kt = 0; kt < 7; kt++) {
                if (kt >= NT / 2) break;
                uint32_t a[4] = { ph[2 * kt][0], ph[2 * kt][1],
                                  ph[2 * kt + 1][0], ph[2 * kt + 1][1] };
                uint32_t v0f[4], v1f[4];
                ldsm_x4_t(v0f, vb + (uint32_t)((base8 + kt * 16 + a_row_off) * 80 + a_cg));
                ldsm_x4_t(v1f, vb + (uint32_t)((base8 + kt * 16 + a_row_off) * 80 + a_cg + 32));
                mma_f16(o[0], a, &v0f[0]);
                mma_f16(o[1], a, &v0f[2]);
                mma_f16(o[2], a, &v1f[0]);
                mma_f16(o[3], a, &v1f[2]);
            }
        }

        const float inv0 = 1.0f / s0;
        const float inv1 = 1.0f / s1;
        const int rr0 = m0 + rq, rr1 = m0 + rq + 8;
#pragma unroll
        for (int n = 0; n < 4; n++) {
            const int col = hdi * HD + n * 8 + cq2;
            if (rr0 < NTOK)
                *(__half2*)(ATT + ((size_t)wi * NTOK + rr0) * DIM + col) =
                    __halves2half2(__float2half_rn(o[n][0] * inv0), __float2half_rn(o[n][1] * inv0));
            if (rr1 < NTOK)
                *(__half2*)(ATT + ((size_t)wi * NTOK + rr1) * DIM + col) =
                    __halves2half2(__float2half_rn(o[n][2] * inv1), __float2half_rn(o[n][3] * inv1));
        }
    }
}

// ---------------------------------------------------------------------------
// Launch
// ---------------------------------------------------------------------------
extern "C" void kernel_launch(void* const* d_in, const int* in_sizes, int n_in,
                              void* d_out, int out_size)
{
    const float* x      = (const float*)d_in[0];
    const float* conv_w = (const float*)d_in[1];
    const float* conv_b = (const float*)d_in[2];
    const float* ln1_g  = (const float*)d_in[3];
    const float* ln1_b  = (const float*)d_in[4];
    const float* qkv_w  = (const float*)d_in[5];
    const float* qkv_b  = (const float*)d_in[6];
    const float* proj_w = (const float*)d_in[7];
    const float* proj_b = (const float*)d_in[8];
    const float* ln2_g  = (const float*)d_in[9];
    const float* ln2_b  = (const float*)d_in[10];
    const float* fc1_w  = (const float*)d_in[11];
    const float* fc1_b  = (const float*)d_in[12];
    const float* fc2_w  = (const float*)d_in[13];
    const float* fc2_b  = (const float*)d_in[14];
    float* out = (float*)d_out;

    __half *X0, *X1, *Y, *QKV, *ATT, *F, *Wh;
    cudaGetSymbolAddress((void**)&X0,  g_X0);
    cudaGetSymbolAddress((void**)&Y,   g_Y);
    cudaGetSymbolAddress((void**)&QKV, g_QKV);
    cudaGetSymbolAddress((void**)&ATT, g_ATT);
    cudaGetSymbolAddress((void**)&X1,  g_X1);
    cudaGetSymbolAddress((void**)&F,   g_F);
    cudaGetSymbolAddress((void**)&Wh,  g_Wh);

    cudaFuncSetAttribute(attn_h_kernel, cudaFuncAttributeMaxDynamicSharedMemorySize, ATTN_SMEM);
    cudaFuncSetAttribute(hgemm_kernel<1152, 384, 0, 0>, cudaFuncAttributeMaxDynamicSharedMemorySize, GEMM_SMEM);
    cudaFuncSetAttribute(hgemm_kernel<384, 384, 0, 0>,  cudaFuncAttributeMaxDynamicSharedMemorySize, GEMM_SMEM);
    cudaFuncSetAttribute(hgemm_kernel<1536, 384, 1, 0>, cudaFuncAttributeMaxDynamicSharedMemorySize, GEMM_SMEM);
    cudaFuncSetAttribute(hgemm_kernel<384, 1536, 0, 2>, cudaFuncAttributeMaxDynamicSharedMemorySize, GEMM_SMEM);

    // 0) fp16 weights
    cvtw_all_kernel<<<(1769472 + 255) / 256, 256>>>(qkv_w, proj_w, fc1_w, fc2_w, Wh);

    // 1) conv PE + residual -> X0 (fp16, 8 rows/CTA)
    conv_pe_kernel<<<dim3(DIM / 8, HH / 8, BATCH), dim3(8, 56)>>>(x, conv_w, conv_b, X0);

    // 2) LN1 -> Y (512-thread blocks)
    ln_kernel<<<TOK / 16, 512>>>(X0, ln1_g, ln1_b, Y);

    // 3) QKV GEMM
    hgemm_kernel<1152, 384, 0, 0><<<dim3(1152 / BN, TOK / BM), 256, GEMM_SMEM>>>(
        Y, Wh + WOFF_QKV, qkv_b, nullptr, nullptr, QKV);

    // 4) window attention
    attn_h_kernel<<<NWIN * NH, 256, ATTN_SMEM>>>(QKV, ATT);

    // 5) proj GEMM + residual(X0) -> X1 (fp16)
    hgemm_kernel<384, 384, 0, 0><<<dim3(384 / BN, TOK / BM), 256, GEMM_SMEM>>>(
        ATT, Wh + WOFF_PROJ, proj_b, X0, nullptr, X1);

    // 6) LN2 -> Y
    ln_kernel<<<TOK / 16, 512>>>(X1, ln2_g, ln2_b, Y);

    // 7) FC1 GEMM + GELU -> F (fp16)
    hgemm_kernel<1536, 384, 1, 0><<<dim3(1536 / BN, TOK / BM), 256, GEMM_SMEM>>>(
        Y, Wh + WOFF_FC1, fc1_b, nullptr, nullptr, F);

    // 8) FC2 GEMM + residual(X1) -> out (BCHW scatter, fp32)
    hgemm_kernel<384, 1536, 0, 2><<<dim3(384 / BN, TOK / BM), 256, GEMM_SMEM>>>(
        F, Wh + WOFF_FC2, fc2_b, X1, out, nullptr);
}